// round 5
// baseline (speedup 1.0000x reference)
#include <cuda_runtime.h>
#include <math.h>

// Problem constants (fixed shapes)
#define DN 32
#define HN 192
#define WN 192
#define DHW (DN*HN*WN)      // 1179648
#define BN 4
#define CN 7
#define NID 16
#define NBI (BN*NID)        // 64
#define NB 4096             // histogram bins over e in [0,2]
#define SLICES 7
#define CH ((DHW + SLICES - 1) / SLICES)   // 168522

// ---------------- device scratch (static; no allocations) ----------------
__device__ float4 g_se[(size_t)BN*DHW];                  // tanh(pred[:3])+xyzm, seed(+id in low mantissa)
__device__ unsigned long long g_part[NBI][SLICES][2*NB]; // per-slice packed histograms
__device__ double g_acc[NBI][10];
__device__ double g_bg[BN];
__device__ double g_seedl[BN];
__device__ double g_instl[BN];
__device__ float  g_center[NBI][3];
__device__ float  g_sexp[NBI][3];
__device__ float  g_cnt[NBI];
__device__ float  g_varsum[BN];
__device__ float  g_denom[BN];

// ---------------- zero the small accumulators only ----------------
__global__ void kzero() {
    int t = threadIdx.x;
    double* acc = &g_acc[0][0];
    if (t < NBI*10) acc[t] = 0.0;
    if (t < BN) { g_bg[t] = 0.0; g_seedl[t] = 0.0; g_instl[t] = 0.0; }
}

// ---------------- pass 1: preprocess + per-instance accumulators ----------------
// per-warp replica accumulators: no inter-warp shared-atomic contention
__global__ void __launch_bounds__(256) k1(const float* __restrict__ pred,
                                          const int* __restrict__ inst,
                                          const int* __restrict__ lab,
                                          const float* __restrict__ xyzm) {
    __shared__ float sacc[8][NID*10];    // one replica per warp (20KB)
    __shared__ float swr[8];
    int tid = threadIdx.x;
    for (int i = tid; i < 8*NID*10; i += 256) (&sacc[0][0])[i] = 0.f;
    __syncthreads();
    float* my = sacc[tid >> 5];

    int b = blockIdx.y;
    const float* pb = pred + (size_t)b * CN * DHW;
    const int*   ib = inst + (size_t)b * DHW;
    const int*   lb = lab  + (size_t)b * DHW;
    float bgl = 0.f;

    for (int v = blockIdx.x * blockDim.x + tid; v < DHW; v += gridDim.x * blockDim.x) {
        float p0 = pb[v], p1 = pb[DHW+v], p2 = pb[2*DHW+v];
        float s0 = pb[3*DHW+v], s1 = pb[4*DHW+v], s2 = pb[5*DHW+v];
        float p6 = pb[6*DHW+v];
        float xm = xyzm[v], ym = xyzm[DHW+v], zm = xyzm[2*DHW+v];
        float e0 = tanhf(p0) + xm;
        float e1 = tanhf(p1) + ym;
        float e2 = tanhf(p2) + zm;
        float seed = 1.f / (1.f + __expf(-p6));

        int id = ib[v];
        // pack id into low 5 mantissa bits of seed (relative error 2^-19)
        unsigned wbits = (__float_as_uint(seed) & ~31u) | (unsigned)id;
        g_se[(size_t)b*DHW + v] = make_float4(e0, e1, e2, __uint_as_float(wbits));

        if (id > 0) {
            float* s = &my[(id-1)*10];
            atomicAdd(s+0, 1.f);
            atomicAdd(s+1, xm); atomicAdd(s+2, ym); atomicAdd(s+3, zm);
            atomicAdd(s+4, s0); atomicAdd(s+5, s1); atomicAdd(s+6, s2);
            atomicAdd(s+7, s0*s0); atomicAdd(s+8, s1*s1); atomicAdd(s+9, s2*s2);
        }
        if (lb[v] == 0) bgl += seed * seed;
    }
    // warp-reduce bg
    for (int o = 16; o; o >>= 1) bgl += __shfl_down_sync(0xffffffffu, bgl, o);
    if ((tid & 31) == 0) swr[tid >> 5] = bgl;
    __syncthreads();
    if (tid == 0) {
        double s = 0.0;
        for (int i = 0; i < 8; i++) s += (double)swr[i];
        atomicAdd(&g_bg[b], s);
    }
    // merge 8 replicas -> global
    for (int i = tid; i < NID*10; i += 256) {
        float s = 0.f;
        #pragma unroll
        for (int r = 0; r < 8; r++) s += sacc[r][i];
        atomicAdd(&g_acc[b*NID + i/10][i%10], (double)s);
    }
}

// ---------------- pass 2: per-instance stats ----------------
__global__ void k2() {
    __shared__ float sobj[BN], svar[BN];
    int t = threadIdx.x;            // 0..63  (b*16 + (id-1))
    if (t < BN) { sobj[t] = 0.f; svar[t] = 0.f; }
    __syncthreads();
    int b = t / NID;

    double cnt = g_acc[t][0];
    bool ex = cnt > 0.0;
    double safe = cnt > 1.0 ? cnt : 1.0;
    double c0 = g_acc[t][1] / safe, c1 = g_acc[t][2] / safe, c2 = g_acc[t][3] / safe;
    double m0 = g_acc[t][4] / safe, m1 = g_acc[t][5] / safe, m2 = g_acc[t][6] / safe;
    double var = 0.0;
    if (ex) {
        var = ((g_acc[t][7] - cnt*m0*m0) +
               (g_acc[t][8] - cnt*m1*m1) +
               (g_acc[t][9] - cnt*m2*m2)) / (3.0 * safe);
    }
    g_center[t][0] = (float)c0; g_center[t][1] = (float)c1; g_center[t][2] = (float)c2;
    g_sexp[t][0] = expf((float)(m0 * 10.0));
    g_sexp[t][1] = expf((float)(m1 * 10.0));
    g_sexp[t][2] = expf((float)(m2 * 10.0));
    g_cnt[t] = ex ? (float)cnt : 0.f;

    atomicAdd(&sobj[b], ex ? 1.f : 0.f);
    atomicAdd(&svar[b], (float)var);
    __syncthreads();
    if (t < BN) {
        g_denom[t]  = sobj[t] > 1.f ? sobj[t] : 1.f;
        g_varsum[t] = svar[t];
    }
}

// ---------------- pass 3: per-(b,id,slice) histograms + seed loss ----------------
// warp-aggregated shared atomics: lanes matching on bin merge via REDUX, leader
// issues one packed atomic (groupCount<<32 | residualSum)
__global__ void __launch_bounds__(512, 3) k3() {
    extern __shared__ unsigned long long sh[];     // 2*NB u64 = 64KB
    __shared__ float swr[16];

    int b = blockIdx.z, idm1 = blockIdx.x;
    int bi = b * NID + idm1;
    unsigned id = idm1 + 1;
    float G = g_cnt[bi];
    if (G == 0.f) return;

    float c0 = g_center[bi][0], c1 = g_center[bi][1], c2 = g_center[bi][2];
    float e0 = g_sexp[bi][0],   e1 = g_sexp[bi][1],   e2 = g_sexp[bi][2];

    int tid = threadIdx.x;
    int lane = tid & 31;
    for (int i = tid; i < 2*NB; i += 512) sh[i] = 0ULL;
    __syncthreads();

    const float4* __restrict__ se = g_se + (size_t)b * DHW;
    float sacc = 0.f;
    int v0 = blockIdx.y * CH;
    int vend = v0 + CH; if (vend > DHW) vend = DHW;
    int niter = (vend - v0 + 511) >> 9;

    int v = v0 + tid;
    for (int it = 0; it < niter; ++it, v += 512) {
        bool act = v < vend;
        float4 S = act ? se[v] : make_float4(1e9f, 1e9f, 1e9f, 0.f);
        unsigned iv = __float_as_uint(S.w) & 31u;
        float dx = S.x - c0, dy = S.y - c1, dz = S.z - c2;
        float d2 = fmaf(dx*dx, e0, fmaf(dy*dy, e1, dz*dz*e2));
        float dist = __expf(-d2);
        bool gt = (iv == id);
        float t = gt ? (4096.f - 4096.f*dist) : (4096.f*dist);
        unsigned ti = __float2uint_rz(t * 16384.f);
        ti = ti > 67108863u ? 67108863u : ti;
        unsigned off = (ti >> 14) + (gt ? NB : 0);
        if (!act) off = 0xffffffffu;                       // sentinel group, no atomic
        unsigned grp  = __match_any_sync(0xffffffffu, off);
        unsigned rsum = __reduce_add_sync(grp, ti & 16383u);
        unsigned cg   = __popc(grp);
        if (act && lane == (__ffs(grp) - 1))
            atomicAdd(&sh[off], ((unsigned long long)cg << 32) | (unsigned long long)rsum);
        if (gt) { float df = S.w - dist; sacc += df * df; }
    }

    // warp-reduce seed loss
    for (int o = 16; o; o >>= 1) sacc += __shfl_down_sync(0xffffffffu, sacc, o);
    if (lane == 0) swr[tid >> 5] = sacc;
    __syncthreads();
    if (tid == 0) {
        double s = 0.0;
        for (int i = 0; i < 16; i++) s += (double)swr[i];
        atomicAdd(&g_seedl[b], s);
    }
    // dump partial histogram (plain stores, no atomics)
    unsigned long long* dst = g_part[bi][blockIdx.y];
    for (int i = tid; i < 2*NB; i += 512) dst[i] = sh[i];
}

// ---------------- pass 4: Lovasz via histogram scan ----------------
#define NT4 512
#define PER4 (NB / NT4)   // 8
__global__ void k4() {
    extern __shared__ float sf[];   // pc[NB], nc[NB], ps[NB], ns[NB] = 64KB
    float* pc = sf;
    float* nc = sf + NB;
    float* ps = sf + 2*NB;
    float* ns = sf + 3*NB;
    __shared__ float sp[NT4], sn[NT4];
    __shared__ double sctr[NT4];

    int bi = blockIdx.x, b = bi / NID;
    float G = g_cnt[bi];
    if (G == 0.f) return;
    int t = threadIdx.x;

    float tp = 0.f, tn = 0.f;
    #pragma unroll
    for (int i = 0; i < PER4; i++) {
        int k = t * PER4 + i;        // descending-order position
        int j = NB - 1 - k;          // bin index
        unsigned long long cp = 0, rp = 0, cn = 0, rn = 0;
        #pragma unroll
        for (int s = 0; s < SLICES; s++) {
            unsigned long long vp = g_part[bi][s][NB + j];
            unsigned long long vn = g_part[bi][s][j];
            cp += vp >> 32; rp += vp & 0xffffffffULL;
            cn += vn >> 32; rn += vn & 0xffffffffULL;
        }
        float fp = (float)cp, fn = (float)cn;
        pc[k] = fp; nc[k] = fn;
        ps[k] = (float)(((double)cp * (double)j + (double)rp * (1.0/16384.0)) * (1.0/2048.0));
        ns[k] = (float)(((double)cn * (double)j + (double)rn * (1.0/16384.0)) * (1.0/2048.0));
        tp += fp; tn += fn;
    }
    sp[t] = tp; sn[t] = tn;
    __syncthreads();
    for (int o = 1; o < NT4; o <<= 1) {
        float ap = (t >= o) ? sp[t - o] : 0.f;
        float an = (t >= o) ? sn[t - o] : 0.f;
        __syncthreads();
        sp[t] += ap; sn[t] += an;
        __syncthreads();
    }
    float P = sp[t] - tp;   // exclusive cumulative positives before this thread's bins
    float N = sn[t] - tn;

    double contrib = 0.0;
    #pragma unroll
    for (int i = 0; i < PER4; i++) {
        int k = t * PER4 + i;
        float p = pc[k], n = nc[k];
        double U0 = (double)G + (double)N;
        double U1 = U0 + (double)n;
        // average of pos-first and neg-first within-bin orderings:
        if (p > 0.f) contrib += (double)ps[k] * 0.5 * (1.0/U0 + 1.0/U1);
        if (n > 0.f) contrib += (double)ns[k] *
                                ((double)G - (double)P - 0.5*(double)p) / (U0 * U1);
        P += p; N += n;
    }
    sctr[t] = contrib;
    __syncthreads();
    for (int o = NT4/2; o > 0; o >>= 1) {
        if (t < o) sctr[t] += sctr[t + o];
        __syncthreads();
    }
    if (t == 0) atomicAdd(&g_instl[b], sctr[0]);
}

// ---------------- pass 5: final reduction ----------------
__global__ void k5(float* __restrict__ out) {
    double li = 0.0, lv = 0.0, ls = 0.0;
    for (int b = 0; b < BN; b++) {
        li += g_instl[b] / (double)g_denom[b];
        lv += (double)g_varsum[b] / (double)g_denom[b];
        ls += (g_seedl[b] + g_bg[b]) / (double)DHW;
    }
    li /= (double)BN;
    lv = lv * 10.0 / (double)BN;   // W_VAR = 10
    ls /= (double)BN;
    out[0] = (float)li;
    out[1] = (float)lv;
    out[2] = (float)ls;
    out[3] = (float)(li + lv + ls);
}

// ---------------- launch ----------------
extern "C" void kernel_launch(void* const* d_in, const int* in_sizes, int n_in,
                              void* d_out, int out_size) {
    const float* pred = (const float*)d_in[0];
    const int*   inst = (const int*)d_in[1];
    const int*   lab  = (const int*)d_in[2];
    // d_in[3] = center_images (unused by the loss)
    const float* xyzm = (const float*)d_in[4];

    cudaFuncSetAttribute(k3, cudaFuncAttributeMaxDynamicSharedMemorySize, 2*NB*8);
    cudaFuncSetAttribute(k4, cudaFuncAttributeMaxDynamicSharedMemorySize, 4*NB*4);

    kzero<<<1, 640>>>();
    k1<<<dim3(288, BN), 256>>>(pred, inst, lab, xyzm);
    k2<<<1, 64>>>();
    k3<<<dim3(NID, SLICES, BN), 512, 2*NB*8>>>();
    k4<<<NBI, NT4, 4*NB*4>>>();
    k5<<<1, 1>>>((float*)d_out);
}

// round 6
// speedup vs baseline: 4.4828x; 4.4828x over previous
#include <cuda_runtime.h>
#include <math.h>

// Problem constants (fixed shapes)
#define DN 32
#define HN 192
#define WN 192
#define DHW (DN*HN*WN)      // 1179648
#define BN 4
#define CN 7
#define NID 16
#define NBI (BN*NID)        // 64
#define NB 4096             // histogram bins over e in [0,2]
#define SLICES 7
#define CH ((DHW + SLICES - 1) / SLICES)   // 168522

// ---------------- device scratch (static; no allocations) ----------------
__device__ float4 g_se[(size_t)BN*DHW];                  // tanh(pred[:3])+xyzm, seed(+id in low mantissa)
__device__ unsigned long long g_part[NBI][SLICES][2*NB]; // per-slice packed histograms
__device__ double g_acc[NBI][10];
__device__ double g_bg[BN];
__device__ double g_seedl[BN];
__device__ double g_instl[BN];
__device__ float  g_center[NBI][3];
__device__ float  g_sexp[NBI][3];
__device__ float  g_cnt[NBI];
__device__ float  g_varsum[BN];
__device__ float  g_denom[BN];

// ---------------- zero the small accumulators only ----------------
__global__ void kzero() {
    int t = threadIdx.x;
    double* acc = &g_acc[0][0];
    if (t < NBI*10) acc[t] = 0.0;
    if (t < BN) { g_bg[t] = 0.0; g_seedl[t] = 0.0; g_instl[t] = 0.0; }
}

// fixed-point packing scales (per-warp accumulation, 8-replica merge headroom)
#define SCP 524288.0f    // 2^19  positions in [0,1]
#define SCS 16384.0f     // 2^14  sigma biased +16, in [0,32]
#define SCQ 8192.0f      // 2^13  sigma^2
__device__ __forceinline__ unsigned long long pk2(float hi, float lo) {
    return ((unsigned long long)__float2uint_rn(hi) << 32) | (unsigned long long)__float2uint_rn(lo);
}

// ---------------- pass 1: preprocess + per-instance accumulators ----------------
// u64 packed pairs (5 atomics per fg voxel) into per-warp replica banks:
//   [0] x<<32 | y            [1] z<<32 | (s0+16)
//   [2] (s1+16)<<32 | (s2+16)
//   [3] s0^2<<32 | s1^2      [4] s2^2<<32 | cnt
__global__ void __launch_bounds__(256) k1(const float* __restrict__ pred,
                                          const int* __restrict__ inst,
                                          const int* __restrict__ lab,
                                          const float* __restrict__ xyzm) {
    __shared__ unsigned long long sacc[8][NID*5];   // one replica per warp (5KB)
    __shared__ unsigned long long stot[NID*5];
    __shared__ float swr[8];
    int tid = threadIdx.x;
    for (int i = tid; i < 8*NID*5; i += 256) (&sacc[0][0])[i] = 0ULL;
    __syncthreads();
    unsigned long long* my = sacc[tid >> 5];

    int b = blockIdx.y;
    const float* pb = pred + (size_t)b * CN * DHW;
    const int*   ib = inst + (size_t)b * DHW;
    const int*   lb = lab  + (size_t)b * DHW;
    float bgl = 0.f;

    for (int v = blockIdx.x * blockDim.x + tid; v < DHW; v += gridDim.x * blockDim.x) {
        float p0 = pb[v], p1 = pb[DHW+v], p2 = pb[2*DHW+v];
        float s0 = pb[3*DHW+v], s1 = pb[4*DHW+v], s2 = pb[5*DHW+v];
        float p6 = pb[6*DHW+v];
        float xm = xyzm[v], ym = xyzm[DHW+v], zm = xyzm[2*DHW+v];
        float e0 = tanhf(p0) + xm;
        float e1 = tanhf(p1) + ym;
        float e2 = tanhf(p2) + zm;
        float seed = 1.f / (1.f + __expf(-p6));

        int id = ib[v];
        // pack id into low 5 mantissa bits of seed (relative error 2^-19)
        unsigned wbits = (__float_as_uint(seed) & ~31u) | (unsigned)id;
        g_se[(size_t)b*DHW + v] = make_float4(e0, e1, e2, __uint_as_float(wbits));

        if (id > 0) {
            unsigned long long* s = &my[(id-1)*5];
            atomicAdd(&s[0], pk2(xm*SCP, ym*SCP));
            atomicAdd(&s[1], pk2(zm*SCP, (s0+16.f)*SCS));
            atomicAdd(&s[2], pk2((s1+16.f)*SCS, (s2+16.f)*SCS));
            atomicAdd(&s[3], pk2(s0*s0*SCQ, s1*s1*SCQ));
            atomicAdd(&s[4], (((unsigned long long)__float2uint_rn(s2*s2*SCQ)) << 32) | 1ULL);
        }
        if (lb[v] == 0) bgl += seed * seed;
    }
    // warp-reduce bg
    for (int o = 16; o; o >>= 1) bgl += __shfl_down_sync(0xffffffffu, bgl, o);
    if ((tid & 31) == 0) swr[tid >> 5] = bgl;
    __syncthreads();
    if (tid == 0) {
        double s = 0.0;
        for (int i = 0; i < 8; i++) s += (double)swr[i];
        atomicAdd(&g_bg[b], s);
    }
    // sum replicas (no cross-field carries: per-field sums stay < 2^32)
    for (int i = tid; i < NID*5; i += 256) {
        unsigned long long s = 0ULL;
        #pragma unroll
        for (int r = 0; r < 8; r++) s += sacc[r][i];
        stot[i] = s;
    }
    __syncthreads();
    // decode + merge (thread i handles id i)
    if (tid < NID) {
        unsigned long long A = stot[tid*5+0], Bv = stot[tid*5+1], Cv = stot[tid*5+2],
                           Dv = stot[tid*5+3], E = stot[tid*5+4];
        double cnt = (double)(unsigned)(E & 0xffffffffULL);
        if (cnt > 0.0) {
            double sx = (double)(unsigned)(A >> 32) / (double)SCP;
            double sy = (double)(unsigned)(A & 0xffffffffULL) / (double)SCP;
            double sz = (double)(unsigned)(Bv >> 32) / (double)SCP;
            double ss0 = (double)(unsigned)(Bv & 0xffffffffULL) / (double)SCS - 16.0 * cnt;
            double ss1 = (double)(unsigned)(Cv >> 32) / (double)SCS - 16.0 * cnt;
            double ss2 = (double)(unsigned)(Cv & 0xffffffffULL) / (double)SCS - 16.0 * cnt;
            double q0 = (double)(unsigned)(Dv >> 32) / (double)SCQ;
            double q1 = (double)(unsigned)(Dv & 0xffffffffULL) / (double)SCQ;
            double q2 = (double)(unsigned)(E >> 32) / (double)SCQ;
            double* g = g_acc[b*NID + tid];
            atomicAdd(&g[0], cnt);
            atomicAdd(&g[1], sx); atomicAdd(&g[2], sy); atomicAdd(&g[3], sz);
            atomicAdd(&g[4], ss0); atomicAdd(&g[5], ss1); atomicAdd(&g[6], ss2);
            atomicAdd(&g[7], q0); atomicAdd(&g[8], q1); atomicAdd(&g[9], q2);
        }
    }
}

// ---------------- pass 2: per-instance stats ----------------
__global__ void k2() {
    __shared__ float sobj[BN], svar[BN];
    int t = threadIdx.x;            // 0..63  (b*16 + (id-1))
    if (t < BN) { sobj[t] = 0.f; svar[t] = 0.f; }
    __syncthreads();
    int b = t / NID;

    double cnt = g_acc[t][0];
    bool ex = cnt > 0.0;
    double safe = cnt > 1.0 ? cnt : 1.0;
    double c0 = g_acc[t][1] / safe, c1 = g_acc[t][2] / safe, c2 = g_acc[t][3] / safe;
    double m0 = g_acc[t][4] / safe, m1 = g_acc[t][5] / safe, m2 = g_acc[t][6] / safe;
    double var = 0.0;
    if (ex) {
        var = ((g_acc[t][7] - cnt*m0*m0) +
               (g_acc[t][8] - cnt*m1*m1) +
               (g_acc[t][9] - cnt*m2*m2)) / (3.0 * safe);
    }
    g_center[t][0] = (float)c0; g_center[t][1] = (float)c1; g_center[t][2] = (float)c2;
    g_sexp[t][0] = expf((float)(m0 * 10.0));
    g_sexp[t][1] = expf((float)(m1 * 10.0));
    g_sexp[t][2] = expf((float)(m2 * 10.0));
    g_cnt[t] = ex ? (float)cnt : 0.f;

    atomicAdd(&sobj[b], ex ? 1.f : 0.f);
    atomicAdd(&svar[b], (float)var);
    __syncthreads();
    if (t < BN) {
        g_denom[t]  = sobj[t] > 1.f ? sobj[t] : 1.f;
        g_varsum[t] = svar[t];
    }
}

// ---------------- pass 3: per-(b,id,slice) histograms + seed loss ----------------
// one packed u64 shared atomic per voxel: (count<<32) | (ti & 16383)
// ti = floor(t*16384), t = e*2048 in [0,4096)
#define K3_BODY(S)                                                              \
    {                                                                           \
        unsigned iv = __float_as_uint(S.w) & 31u;                               \
        float dx = S.x - c0, dy = S.y - c1, dz = S.z - c2;                      \
        float d2 = fmaf(dx*dx, e0, fmaf(dy*dy, e1, dz*dz*e2));                  \
        float dist = __expf(-d2);                                               \
        bool gt = (iv == id);                                                   \
        float t = gt ? (4096.f - 4096.f*dist) : (4096.f*dist);                  \
        unsigned ti = __float2uint_rz(t * 16384.f);                             \
        ti = ti > 67108863u ? 67108863u : ti;                                   \
        unsigned off = (ti >> 14) + (gt ? NB : 0);                              \
        atomicAdd(&sh[off], (1ULL << 32) | (unsigned long long)(ti & 16383u));  \
        if (gt) { float df = S.w - dist; sacc += df * df; }                     \
    }

__global__ void __launch_bounds__(512, 3) k3() {
    extern __shared__ unsigned long long sh[];     // 2*NB u64 = 64KB
    __shared__ float swr[16];

    int b = blockIdx.z, idm1 = blockIdx.x;
    int bi = b * NID + idm1;
    unsigned id = idm1 + 1;
    float G = g_cnt[bi];
    if (G == 0.f) return;

    float c0 = g_center[bi][0], c1 = g_center[bi][1], c2 = g_center[bi][2];
    float e0 = g_sexp[bi][0],   e1 = g_sexp[bi][1],   e2 = g_sexp[bi][2];

    int tid = threadIdx.x;
    for (int i = tid; i < 2*NB; i += 512) sh[i] = 0ULL;
    __syncthreads();

    const float4* __restrict__ se = g_se + (size_t)b * DHW;
    float sacc = 0.f;
    int v0 = blockIdx.y * CH;
    int vend = v0 + CH; if (vend > DHW) vend = DHW;

    int v = v0 + tid;
    for (; v + 512 < vend; v += 1024) {
        float4 sA = se[v];
        float4 sB = se[v + 512];
        K3_BODY(sA)
        K3_BODY(sB)
    }
    for (; v < vend; v += 512) {
        float4 sA = se[v];
        K3_BODY(sA)
    }

    // warp-reduce seed loss
    for (int o = 16; o; o >>= 1) sacc += __shfl_down_sync(0xffffffffu, sacc, o);
    if ((tid & 31) == 0) swr[tid >> 5] = sacc;
    __syncthreads();
    if (tid == 0) {
        double s = 0.0;
        for (int i = 0; i < 16; i++) s += (double)swr[i];
        atomicAdd(&g_seedl[b], s);
    }
    // dump partial histogram (plain stores, no atomics)
    unsigned long long* dst = g_part[bi][blockIdx.y];
    for (int i = tid; i < 2*NB; i += 512) dst[i] = sh[i];
}

// ---------------- pass 4: Lovasz via histogram scan ----------------
#define NT4 512
#define PER4 (NB / NT4)   // 8
__global__ void k4() {
    extern __shared__ float sf[];   // pc[NB], nc[NB], ps[NB], ns[NB] = 64KB
    float* pc = sf;
    float* nc = sf + NB;
    float* ps = sf + 2*NB;
    float* ns = sf + 3*NB;
    __shared__ float sp[NT4], sn[NT4];
    __shared__ double sctr[NT4];

    int bi = blockIdx.x, b = bi / NID;
    float G = g_cnt[bi];
    if (G == 0.f) return;
    int t = threadIdx.x;

    float tp = 0.f, tn = 0.f;
    #pragma unroll
    for (int i = 0; i < PER4; i++) {
        int k = t * PER4 + i;        // descending-order position
        int j = NB - 1 - k;          // bin index
        unsigned long long cp = 0, rp = 0, cn = 0, rn = 0;
        #pragma unroll
        for (int s = 0; s < SLICES; s++) {
            unsigned long long vp = g_part[bi][s][NB + j];
            unsigned long long vn = g_part[bi][s][j];
            cp += vp >> 32; rp += vp & 0xffffffffULL;
            cn += vn >> 32; rn += vn & 0xffffffffULL;
        }
        float fp = (float)cp, fn = (float)cn;
        pc[k] = fp; nc[k] = fn;
        ps[k] = (float)(((double)cp * (double)j + (double)rp * (1.0/16384.0)) * (1.0/2048.0));
        ns[k] = (float)(((double)cn * (double)j + (double)rn * (1.0/16384.0)) * (1.0/2048.0));
        tp += fp; tn += fn;
    }
    sp[t] = tp; sn[t] = tn;
    __syncthreads();
    for (int o = 1; o < NT4; o <<= 1) {
        float ap = (t >= o) ? sp[t - o] : 0.f;
        float an = (t >= o) ? sn[t - o] : 0.f;
        __syncthreads();
        sp[t] += ap; sn[t] += an;
        __syncthreads();
    }
    float P = sp[t] - tp;   // exclusive cumulative positives before this thread's bins
    float N = sn[t] - tn;

    double contrib = 0.0;
    #pragma unroll
    for (int i = 0; i < PER4; i++) {
        int k = t * PER4 + i;
        float p = pc[k], n = nc[k];
        double U0 = (double)G + (double)N;
        double U1 = U0 + (double)n;
        // average of pos-first and neg-first within-bin orderings:
        if (p > 0.f) contrib += (double)ps[k] * 0.5 * (1.0/U0 + 1.0/U1);
        if (n > 0.f) contrib += (double)ns[k] *
                                ((double)G - (double)P - 0.5*(double)p) / (U0 * U1);
        P += p; N += n;
    }
    sctr[t] = contrib;
    __syncthreads();
    for (int o = NT4/2; o > 0; o >>= 1) {
        if (t < o) sctr[t] += sctr[t + o];
        __syncthreads();
    }
    if (t == 0) atomicAdd(&g_instl[b], sctr[0]);
}

// ---------------- pass 5: final reduction ----------------
__global__ void k5(float* __restrict__ out) {
    double li = 0.0, lv = 0.0, ls = 0.0;
    for (int b = 0; b < BN; b++) {
        li += g_instl[b] / (double)g_denom[b];
        lv += (double)g_varsum[b] / (double)g_denom[b];
        ls += (g_seedl[b] + g_bg[b]) / (double)DHW;
    }
    li /= (double)BN;
    lv = lv * 10.0 / (double)BN;   // W_VAR = 10
    ls /= (double)BN;
    out[0] = (float)li;
    out[1] = (float)lv;
    out[2] = (float)ls;
    out[3] = (float)(li + lv + ls);
}

// ---------------- launch ----------------
extern "C" void kernel_launch(void* const* d_in, const int* in_sizes, int n_in,
                              void* d_out, int out_size) {
    const float* pred = (const float*)d_in[0];
    const int*   inst = (const int*)d_in[1];
    const int*   lab  = (const int*)d_in[2];
    // d_in[3] = center_images (unused by the loss)
    const float* xyzm = (const float*)d_in[4];

    cudaFuncSetAttribute(k3, cudaFuncAttributeMaxDynamicSharedMemorySize, 2*NB*8);
    cudaFuncSetAttribute(k4, cudaFuncAttributeMaxDynamicSharedMemorySize, 4*NB*4);

    kzero<<<1, 640>>>();
    k1<<<dim3(288, BN), 256>>>(pred, inst, lab, xyzm);
    k2<<<1, 64>>>();
    k3<<<dim3(NID, SLICES, BN), 512, 2*NB*8>>>();
    k4<<<NBI, NT4, 4*NB*4>>>();
    k5<<<1, 1>>>((float*)d_out);
}

// round 8
// speedup vs baseline: 6.7835x; 1.5132x over previous
#include <cuda_runtime.h>
#include <math.h>

// Problem constants (fixed shapes)
#define DN 32
#define HN 192
#define WN 192
#define DHW (DN*HN*WN)      // 1179648
#define BN 4
#define CN 7
#define NID 16
#define NBI (BN*NID)        // 64
#define NB 4096             // histogram bins over e in [0,2]
#define SLICES 13
#define CH ((DHW + SLICES - 1) / SLICES)   // 90743
#define NPAIR (NID/2)       // 8 id-pairs per batch

// ---------------- device scratch (static; no allocations) ----------------
__device__ float4 g_se[(size_t)BN*DHW];             // tanh(pred[:3])+xyzm, seed(+id in low mantissa)
__device__ unsigned g_h32[NBI][SLICES][2*NB];       // per-slice count histograms (27MB)
__device__ double g_acc[NBI][10];
__device__ double g_bg[BN];
__device__ double g_seedl[BN];
__device__ double g_instl[BN];
__device__ float  g_center[NBI][3];
__device__ float  g_sexp[NBI][3];
__device__ float  g_cnt[NBI];
__device__ float  g_varsum[BN];
__device__ float  g_denom[BN];

// ---------------- zero the small accumulators only ----------------
__global__ void kzero() {
    int t = threadIdx.x;
    double* acc = &g_acc[0][0];
    if (t < NBI*10) acc[t] = 0.0;
    if (t < BN) { g_bg[t] = 0.0; g_seedl[t] = 0.0; g_instl[t] = 0.0; }
}

// fixed-point packing scales (per-warp accumulation, 8-replica merge headroom)
#define SCP 524288.0f    // 2^19  positions in [0,1]
#define SCS 16384.0f     // 2^14  sigma biased +16, in [0,32]
#define SCQ 8192.0f      // 2^13  sigma^2
__device__ __forceinline__ unsigned long long pk2(float hi, float lo) {
    return ((unsigned long long)__float2uint_rn(hi) << 32) | (unsigned long long)__float2uint_rn(lo);
}
__device__ __forceinline__ float fast_tanh(float x) {
    return 1.f - __fdividef(2.f, 1.f + __expf(2.f * x));
}

// ---------------- pass 1: preprocess + per-instance accumulators ----------------
__global__ void __launch_bounds__(256) k1(const float* __restrict__ pred,
                                          const int* __restrict__ inst,
                                          const int* __restrict__ lab,
                                          const float* __restrict__ xyzm) {
    __shared__ unsigned long long sacc[8][NID*5];   // one replica per warp (5KB)
    __shared__ unsigned long long stot[NID*5];
    __shared__ float swr[8];
    int tid = threadIdx.x;
    for (int i = tid; i < 8*NID*5; i += 256) (&sacc[0][0])[i] = 0ULL;
    __syncthreads();
    unsigned long long* my = sacc[tid >> 5];

    int b = blockIdx.y;
    const float* pb = pred + (size_t)b * CN * DHW;
    const int*   ib = inst + (size_t)b * DHW;
    const int*   lb = lab  + (size_t)b * DHW;
    float bgl = 0.f;

    for (int v = blockIdx.x * blockDim.x + tid; v < DHW; v += gridDim.x * blockDim.x) {
        float p0 = pb[v], p1 = pb[DHW+v], p2 = pb[2*DHW+v];
        float s0 = pb[3*DHW+v], s1 = pb[4*DHW+v], s2 = pb[5*DHW+v];
        float p6 = pb[6*DHW+v];
        float xm = xyzm[v], ym = xyzm[DHW+v], zm = xyzm[2*DHW+v];
        float e0 = fast_tanh(p0) + xm;
        float e1 = fast_tanh(p1) + ym;
        float e2 = fast_tanh(p2) + zm;
        float seed = 1.f / (1.f + __expf(-p6));

        int id = ib[v];
        // pack id into low 5 mantissa bits of seed (relative error 2^-19)
        unsigned wbits = (__float_as_uint(seed) & ~31u) | (unsigned)id;
        g_se[(size_t)b*DHW + v] = make_float4(e0, e1, e2, __uint_as_float(wbits));

        if (id > 0) {
            unsigned long long* s = &my[(id-1)*5];
            atomicAdd(&s[0], pk2(xm*SCP, ym*SCP));
            atomicAdd(&s[1], pk2(zm*SCP, (s0+16.f)*SCS));
            atomicAdd(&s[2], pk2((s1+16.f)*SCS, (s2+16.f)*SCS));
            atomicAdd(&s[3], pk2(s0*s0*SCQ, s1*s1*SCQ));
            atomicAdd(&s[4], (((unsigned long long)__float2uint_rn(s2*s2*SCQ)) << 32) | 1ULL);
        }
        if (lb[v] == 0) bgl += seed * seed;
    }
    // warp-reduce bg
    for (int o = 16; o; o >>= 1) bgl += __shfl_down_sync(0xffffffffu, bgl, o);
    if ((tid & 31) == 0) swr[tid >> 5] = bgl;
    __syncthreads();
    if (tid == 0) {
        double s = 0.0;
        for (int i = 0; i < 8; i++) s += (double)swr[i];
        atomicAdd(&g_bg[b], s);
    }
    // sum replicas (per-field sums stay < 2^32: no cross-field carries)
    for (int i = tid; i < NID*5; i += 256) {
        unsigned long long s = 0ULL;
        #pragma unroll
        for (int r = 0; r < 8; r++) s += sacc[r][i];
        stot[i] = s;
    }
    __syncthreads();
    // decode + merge (thread i handles id i)
    if (tid < NID) {
        unsigned long long A = stot[tid*5+0], Bv = stot[tid*5+1], Cv = stot[tid*5+2],
                           Dv = stot[tid*5+3], E = stot[tid*5+4];
        double cnt = (double)(unsigned)(E & 0xffffffffULL);
        if (cnt > 0.0) {
            double sx = (double)(unsigned)(A >> 32) / (double)SCP;
            double sy = (double)(unsigned)(A & 0xffffffffULL) / (double)SCP;
            double sz = (double)(unsigned)(Bv >> 32) / (double)SCP;
            double ss0 = (double)(unsigned)(Bv & 0xffffffffULL) / (double)SCS - 16.0 * cnt;
            double ss1 = (double)(unsigned)(Cv >> 32) / (double)SCS - 16.0 * cnt;
            double ss2 = (double)(unsigned)(Cv & 0xffffffffULL) / (double)SCS - 16.0 * cnt;
            double q0 = (double)(unsigned)(Dv >> 32) / (double)SCQ;
            double q1 = (double)(unsigned)(Dv & 0xffffffffULL) / (double)SCQ;
            double q2 = (double)(unsigned)(E >> 32) / (double)SCQ;
            double* g = g_acc[b*NID + tid];
            atomicAdd(&g[0], cnt);
            atomicAdd(&g[1], sx); atomicAdd(&g[2], sy); atomicAdd(&g[3], sz);
            atomicAdd(&g[4], ss0); atomicAdd(&g[5], ss1); atomicAdd(&g[6], ss2);
            atomicAdd(&g[7], q0); atomicAdd(&g[8], q1); atomicAdd(&g[9], q2);
        }
    }
}

// ---------------- pass 2: per-instance stats ----------------
__global__ void k2() {
    __shared__ float sobj[BN], svar[BN];
    int t = threadIdx.x;            // 0..63  (b*16 + (id-1))
    if (t < BN) { sobj[t] = 0.f; svar[t] = 0.f; }
    __syncthreads();
    int b = t / NID;

    double cnt = g_acc[t][0];
    bool ex = cnt > 0.0;
    double safe = cnt > 1.0 ? cnt : 1.0;
    double c0 = g_acc[t][1] / safe, c1 = g_acc[t][2] / safe, c2 = g_acc[t][3] / safe;
    double m0 = g_acc[t][4] / safe, m1 = g_acc[t][5] / safe, m2 = g_acc[t][6] / safe;
    double var = 0.0;
    if (ex) {
        var = ((g_acc[t][7] - cnt*m0*m0) +
               (g_acc[t][8] - cnt*m1*m1) +
               (g_acc[t][9] - cnt*m2*m2)) / (3.0 * safe);
    }
    g_center[t][0] = (float)c0; g_center[t][1] = (float)c1; g_center[t][2] = (float)c2;
    g_sexp[t][0] = expf((float)(m0 * 10.0));
    g_sexp[t][1] = expf((float)(m1 * 10.0));
    g_sexp[t][2] = expf((float)(m2 * 10.0));
    g_cnt[t] = ex ? (float)cnt : 0.f;

    atomicAdd(&sobj[b], ex ? 1.f : 0.f);
    atomicAdd(&svar[b], (float)var);
    __syncthreads();
    if (t < BN) {
        g_denom[t]  = sobj[t] > 1.f ? sobj[t] : 1.f;
        g_varsum[t] = svar[t];
    }
}

// ---------------- pass 3: per-(b,idpair,slice) count histograms + seed loss ----------------
// two instances per CTA: one float4 load serves two id-passes; u32 count atomics
#define K3_PAIR(S)                                                               \
    {                                                                            \
        unsigned iv = __float_as_uint(S.w) & 31u;                                \
        float dxA = S.x - cA0, dyA = S.y - cA1, dzA = S.z - cA2;                 \
        float d2A = fmaf(dxA*dxA, eA0, fmaf(dyA*dyA, eA1, dzA*dzA*eA2));         \
        float distA = __expf(-d2A);                                              \
        bool gtA = (iv == idA);                                                  \
        float uA = distA * 4096.f;                                               \
        int binA = gtA ? (int)(4096.f - uA) : (int)uA;                           \
        binA = binA > NB-1 ? NB-1 : (binA < 0 ? 0 : binA);                       \
        atomicAdd(&shA[(gtA ? NB : 0) + binA], 1u);                              \
        if (gtA) { float df = S.w - distA; sacc += df * df; }                    \
        float dxB = S.x - cB0, dyB = S.y - cB1, dzB = S.z - cB2;                 \
        float d2B = fmaf(dxB*dxB, eB0, fmaf(dyB*dyB, eB1, dzB*dzB*eB2));         \
        float distB = __expf(-d2B);                                              \
        bool gtB = (iv == idB);                                                  \
        float uB = distB * 4096.f;                                               \
        int binB = gtB ? (int)(4096.f - uB) : (int)uB;                           \
        binB = binB > NB-1 ? NB-1 : (binB < 0 ? 0 : binB);                       \
        atomicAdd(&shB[(gtB ? NB : 0) + binB], 1u);                              \
        if (gtB) { float df = S.w - distB; sacc += df * df; }                    \
    }

__global__ void __launch_bounds__(512, 3) k3() {
    extern __shared__ unsigned sh[];     // 2 x 2*NB u32 = 64KB
    unsigned* shA = sh;
    unsigned* shB = sh + 2*NB;
    __shared__ float swr[16];

    int b = blockIdx.z, p = blockIdx.x, s = blockIdx.y;
    int biA = b * NID + 2*p, biB = biA + 1;
    unsigned idA = 2*p + 1, idB = 2*p + 2;
    if (g_cnt[biA] == 0.f && g_cnt[biB] == 0.f) return;

    float cA0 = g_center[biA][0], cA1 = g_center[biA][1], cA2 = g_center[biA][2];
    float eA0 = g_sexp[biA][0],   eA1 = g_sexp[biA][1],   eA2 = g_sexp[biA][2];
    float cB0 = g_center[biB][0], cB1 = g_center[biB][1], cB2 = g_center[biB][2];
    float eB0 = g_sexp[biB][0],   eB1 = g_sexp[biB][1],   eB2 = g_sexp[biB][2];

    int tid = threadIdx.x;
    for (int i = tid; i < 4*NB; i += 512) sh[i] = 0u;
    __syncthreads();

    const float4* __restrict__ se = g_se + (size_t)b * DHW;
    float sacc = 0.f;
    int v0 = s * CH;
    int vend = v0 + CH; if (vend > DHW) vend = DHW;

    int v = v0 + tid;
    for (; v + 512 < vend; v += 1024) {
        float4 S1 = se[v];
        float4 S2 = se[v + 512];
        K3_PAIR(S1)
        K3_PAIR(S2)
    }
    for (; v < vend; v += 512) {
        float4 S1 = se[v];
        K3_PAIR(S1)
    }

    // warp-reduce seed loss (both instances share batch b)
    for (int o = 16; o; o >>= 1) sacc += __shfl_down_sync(0xffffffffu, sacc, o);
    if ((tid & 31) == 0) swr[tid >> 5] = sacc;
    __syncthreads();
    if (tid == 0) {
        double ssum = 0.0;
        for (int i = 0; i < 16; i++) ssum += (double)swr[i];
        atomicAdd(&g_seedl[b], ssum);
    }
    // dump partial histograms (plain stores)
    for (int i = tid; i < 2*NB; i += 512) {
        g_h32[biA][s][i] = shA[i];
        g_h32[biB][s][i] = shB[i];
    }
}

// ---------------- pass 4: Lovasz via histogram scan ----------------
#define NT4 512
#define PER4 (NB / NT4)   // 8
__global__ void k4() {
    __shared__ float pc[NB], nc[NB];     // counts by ascending bin
    __shared__ float sp[NT4], sn[NT4];
    __shared__ double sctr[NT4];

    int bi = blockIdx.x, b = bi / NID;
    float G = g_cnt[bi];
    if (G == 0.f) return;
    int t = threadIdx.x;

    // phase 1: coalesced gather of per-slice counts
    #pragma unroll
    for (int i = 0; i < PER4; i++) {
        int j = i * NT4 + t;             // ascending bin index, coalesced
        unsigned cp = 0, cn_ = 0;
        #pragma unroll
        for (int s = 0; s < SLICES; s++) {
            cp  += g_h32[bi][s][NB + j];
            cn_ += g_h32[bi][s][j];
        }
        pc[j] = (float)cp;
        nc[j] = (float)cn_;
    }
    __syncthreads();

    // phase 2: thread t owns descending positions [t*PER4, t*PER4+PER4)
    float tp = 0.f, tn = 0.f;
    #pragma unroll
    for (int i = 0; i < PER4; i++) {
        int j = NB - 1 - (t * PER4 + i);
        tp += pc[j]; tn += nc[j];
    }
    sp[t] = tp; sn[t] = tn;
    __syncthreads();
    for (int o = 1; o < NT4; o <<= 1) {
        float ap = (t >= o) ? sp[t - o] : 0.f;
        float an = (t >= o) ? sn[t - o] : 0.f;
        __syncthreads();
        sp[t] += ap; sn[t] += an;
        __syncthreads();
    }
    float P = sp[t] - tp;   // exclusive cumulative positives before this thread's bins
    float N = sn[t] - tn;

    double contrib = 0.0;
    #pragma unroll
    for (int i = 0; i < PER4; i++) {
        int j = NB - 1 - (t * PER4 + i);
        float p = pc[j], n = nc[j];
        double ec = ((double)j + 0.5) * (1.0/2048.0);   // bin-center error value
        double U0 = (double)G + (double)N;
        double U1 = U0 + (double)n;
        // average of pos-first and neg-first within-bin orderings:
        if (p > 0.f) contrib += (double)p * ec * 0.5 * (1.0/U0 + 1.0/U1);
        if (n > 0.f) contrib += (double)n * ec *
                                ((double)G - (double)P - 0.5*(double)p) / (U0 * U1);
        P += p; N += n;
    }
    sctr[t] = contrib;
    __syncthreads();
    for (int o = NT4/2; o > 0; o >>= 1) {
        if (t < o) sctr[t] += sctr[t + o];
        __syncthreads();
    }
    if (t == 0) atomicAdd(&g_instl[b], sctr[0]);
}

// ---------------- pass 5: final reduction ----------------
__global__ void k5(float* __restrict__ out) {
    double li = 0.0, lv = 0.0, ls = 0.0;
    for (int b = 0; b < BN; b++) {
        li += g_instl[b] / (double)g_denom[b];
        lv += (double)g_varsum[b] / (double)g_denom[b];
        ls += (g_seedl[b] + g_bg[b]) / (double)DHW;
    }
    li /= (double)BN;
    lv = lv * 10.0 / (double)BN;   // W_VAR = 10
    ls /= (double)BN;
    out[0] = (float)li;
    out[1] = (float)lv;
    out[2] = (float)ls;
    out[3] = (float)(li + lv + ls);
}

// ---------------- launch ----------------
extern "C" void kernel_launch(void* const* d_in, const int* in_sizes, int n_in,
                              void* d_out, int out_size) {
    const float* pred = (const float*)d_in[0];
    const int*   inst = (const int*)d_in[1];
    const int*   lab  = (const int*)d_in[2];
    // d_in[3] = center_images (unused by the loss)
    const float* xyzm = (const float*)d_in[4];

    cudaFuncSetAttribute(k3, cudaFuncAttributeMaxDynamicSharedMemorySize, 4*NB*4);

    kzero<<<1, 640>>>();
    k1<<<dim3(288, BN), 256>>>(pred, inst, lab, xyzm);
    k2<<<1, 64>>>();
    k3<<<dim3(NPAIR, SLICES, BN), 512, 4*NB*4>>>();
    k4<<<NBI, NT4>>>();
    k5<<<1, 1>>>((float*)d_out);
}

// round 9
// speedup vs baseline: 7.0536x; 1.0398x over previous
#include <cuda_runtime.h>
#include <math.h>

// Problem constants (fixed shapes)
#define DN 32
#define HN 192
#define WN 192
#define DHW (DN*HN*WN)      // 1179648
#define BN 4
#define CN 7
#define NID 16
#define NBI (BN*NID)        // 64
#define NB 4096             // histogram bins over e in [0,2]
#define SLICES 13
#define CH ((DHW + SLICES - 1) / SLICES)   // 90743
#define NPAIR (NID/2)       // 8 id-pairs per batch

// ---------------- device scratch (static; no allocations) ----------------
__device__ float4 g_se[(size_t)BN*DHW];             // tanh(pred[:3])+xyzm, seed(+id in low mantissa)
__device__ unsigned g_h32[NBI][SLICES][2*NB];       // per-slice count histograms (27MB)
__device__ double g_acc[NBI][10];
__device__ double g_bg[BN];
__device__ double g_seedl[BN];
__device__ double g_instl[BN];
__device__ float  g_center[NBI][3];
__device__ float  g_sexp[NBI][3];
__device__ float  g_cnt[NBI];
__device__ float  g_varsum[BN];
__device__ float  g_denom[BN];

// ---------------- zero the small accumulators only ----------------
__global__ void kzero() {
    int t = threadIdx.x;
    double* acc = &g_acc[0][0];
    if (t < NBI*10) acc[t] = 0.0;
    if (t < BN) { g_bg[t] = 0.0; g_seedl[t] = 0.0; g_instl[t] = 0.0; }
}

// fixed-point packing scales (per-warp accumulation: <=512 voxels/warp -> fields <= 2^28)
#define SCP 524288.0f    // 2^19  positions in [0,1]
#define SCS 16384.0f     // 2^14  sigma biased +16, in [0,32]
#define SCQ 8192.0f      // 2^13  sigma^2
__device__ __forceinline__ unsigned long long pk2(float hi, float lo) {
    return ((unsigned long long)__float2uint_rn(hi) << 32) | (unsigned long long)__float2uint_rn(lo);
}
__device__ __forceinline__ float fast_tanh(float x) {
    return 1.f - __fdividef(2.f, 1.f + __expf(2.f * x));
}

// ---------------- pass 1: preprocess + per-instance accumulators ----------------
// 4-voxel vectorized; xyzm computed analytically (linspace); per-warp replica banks
#define VOX(p0,p1,p2,s0,s1,s2,p6, idv, lbv, xmv, vi)                            \
    {                                                                           \
        float e0 = fast_tanh(p0) + (xmv);                                       \
        float e1 = fast_tanh(p1) + ym;                                          \
        float e2 = fast_tanh(p2) + zm;                                          \
        float seed = __fdividef(1.f, 1.f + __expf(-(p6)));                      \
        unsigned wb = (__float_as_uint(seed) & ~31u) | (unsigned)(idv);         \
        o4[vi] = make_float4(e0, e1, e2, __uint_as_float(wb));                  \
        if ((idv) > 0) {                                                        \
            unsigned long long* s = &my[((idv)-1)*5];                           \
            atomicAdd(&s[0], pk2((xmv)*SCP, ym*SCP));                           \
            atomicAdd(&s[1], pk2(zm*SCP, ((s0)+16.f)*SCS));                     \
            atomicAdd(&s[2], pk2(((s1)+16.f)*SCS, ((s2)+16.f)*SCS));            \
            atomicAdd(&s[3], pk2((s0)*(s0)*SCQ, (s1)*(s1)*SCQ));                \
            atomicAdd(&s[4], (((unsigned long long)__float2uint_rn((s2)*(s2)*SCQ)) << 32) | 1ULL); \
        }                                                                       \
        if ((lbv) == 0) bgl += seed * seed;                                     \
    }

__global__ void __launch_bounds__(256) k1(const float* __restrict__ pred,
                                          const int* __restrict__ inst,
                                          const int* __restrict__ lab) {
    __shared__ unsigned long long sacc[8][NID*5];   // one replica per warp (5KB)
    __shared__ unsigned long long stot[NID*5];
    __shared__ float swr[8];
    int tid = threadIdx.x;
    for (int i = tid; i < 8*NID*5; i += 256) (&sacc[0][0])[i] = 0ULL;
    __syncthreads();
    unsigned long long* my = sacc[tid >> 5];

    int b = blockIdx.y;
    const float4* __restrict__ p4 = (const float4*)(pred + (size_t)b * CN * DHW);
    const int4*   __restrict__ i4 = (const int4*)(inst + (size_t)b * DHW);
    const int4*   __restrict__ l4 = (const int4*)(lab  + (size_t)b * DHW);
    float4* o4 = g_se + (size_t)b * DHW;
    float bgl = 0.f;
    const int Q = DHW / 4;

    for (int q = blockIdx.x * 256 + tid; q < Q; q += gridDim.x * 256) {
        float4 P0 = p4[q],       P1 = p4[Q+q],   P2 = p4[2*Q+q];
        float4 S0 = p4[3*Q+q],   S1 = p4[4*Q+q], S2 = p4[5*Q+q];
        float4 P6 = p4[6*Q+q];
        int4 ID = i4[q];
        int4 LB = l4[q];
        int v = q * 4;
        int x0 = v % WN;
        int r  = v / WN;
        float ym = (float)(r % HN) * (1.f/(HN-1));
        float zm = (float)(r / HN) * (1.f/(DN-1));
        float xm = (float)x0 * (1.f/(WN-1));
        VOX(P0.x, P1.x, P2.x, S0.x, S1.x, S2.x, P6.x, ID.x, LB.x, xm,                 v+0)
        VOX(P0.y, P1.y, P2.y, S0.y, S1.y, S2.y, P6.y, ID.y, LB.y, xm + 1.f/(WN-1),    v+1)
        VOX(P0.z, P1.z, P2.z, S0.z, S1.z, S2.z, P6.z, ID.z, LB.z, xm + 2.f/(WN-1),    v+2)
        VOX(P0.w, P1.w, P2.w, S0.w, S1.w, S2.w, P6.w, ID.w, LB.w, xm + 3.f/(WN-1),    v+3)
    }
    // warp-reduce bg
    for (int o = 16; o; o >>= 1) bgl += __shfl_down_sync(0xffffffffu, bgl, o);
    if ((tid & 31) == 0) swr[tid >> 5] = bgl;
    __syncthreads();
    if (tid == 0) {
        double s = 0.0;
        for (int i = 0; i < 8; i++) s += (double)swr[i];
        atomicAdd(&g_bg[b], s);
    }
    // sum replicas (per-field sums stay < 2^32: no cross-field carries)
    for (int i = tid; i < NID*5; i += 256) {
        unsigned long long s = 0ULL;
        #pragma unroll
        for (int r = 0; r < 8; r++) s += sacc[r][i];
        stot[i] = s;
    }
    __syncthreads();
    // decode + merge (thread i handles id i)
    if (tid < NID) {
        unsigned long long A = stot[tid*5+0], Bv = stot[tid*5+1], Cv = stot[tid*5+2],
                           Dv = stot[tid*5+3], E = stot[tid*5+4];
        double cnt = (double)(unsigned)(E & 0xffffffffULL);
        if (cnt > 0.0) {
            double sx = (double)(unsigned)(A >> 32) / (double)SCP;
            double sy = (double)(unsigned)(A & 0xffffffffULL) / (double)SCP;
            double sz = (double)(unsigned)(Bv >> 32) / (double)SCP;
            double ss0 = (double)(unsigned)(Bv & 0xffffffffULL) / (double)SCS - 16.0 * cnt;
            double ss1 = (double)(unsigned)(Cv >> 32) / (double)SCS - 16.0 * cnt;
            double ss2 = (double)(unsigned)(Cv & 0xffffffffULL) / (double)SCS - 16.0 * cnt;
            double q0 = (double)(unsigned)(Dv >> 32) / (double)SCQ;
            double q1 = (double)(unsigned)(Dv & 0xffffffffULL) / (double)SCQ;
            double q2 = (double)(unsigned)(E >> 32) / (double)SCQ;
            double* g = g_acc[b*NID + tid];
            atomicAdd(&g[0], cnt);
            atomicAdd(&g[1], sx); atomicAdd(&g[2], sy); atomicAdd(&g[3], sz);
            atomicAdd(&g[4], ss0); atomicAdd(&g[5], ss1); atomicAdd(&g[6], ss2);
            atomicAdd(&g[7], q0); atomicAdd(&g[8], q1); atomicAdd(&g[9], q2);
        }
    }
}

// ---------------- pass 2: per-instance stats ----------------
__global__ void k2() {
    __shared__ float sobj[BN], svar[BN];
    int t = threadIdx.x;            // 0..63  (b*16 + (id-1))
    if (t < BN) { sobj[t] = 0.f; svar[t] = 0.f; }
    __syncthreads();
    int b = t / NID;

    double cnt = g_acc[t][0];
    bool ex = cnt > 0.0;
    double safe = cnt > 1.0 ? cnt : 1.0;
    double c0 = g_acc[t][1] / safe, c1 = g_acc[t][2] / safe, c2 = g_acc[t][3] / safe;
    double m0 = g_acc[t][4] / safe, m1 = g_acc[t][5] / safe, m2 = g_acc[t][6] / safe;
    double var = 0.0;
    if (ex) {
        var = ((g_acc[t][7] - cnt*m0*m0) +
               (g_acc[t][8] - cnt*m1*m1) +
               (g_acc[t][9] - cnt*m2*m2)) / (3.0 * safe);
    }
    g_center[t][0] = (float)c0; g_center[t][1] = (float)c1; g_center[t][2] = (float)c2;
    g_sexp[t][0] = expf((float)(m0 * 10.0));
    g_sexp[t][1] = expf((float)(m1 * 10.0));
    g_sexp[t][2] = expf((float)(m2 * 10.0));
    g_cnt[t] = ex ? (float)cnt : 0.f;

    atomicAdd(&sobj[b], ex ? 1.f : 0.f);
    atomicAdd(&svar[b], (float)var);
    __syncthreads();
    if (t < BN) {
        g_denom[t]  = sobj[t] > 1.f ? sobj[t] : 1.f;
        g_varsum[t] = svar[t];
    }
}

// ---------------- pass 3: per-(b,idpair,slice) count histograms + seed loss ----------------
// two instances per CTA; d4096 = 4096*exp(-d2) via one FFMA+EX2; u32 count atomics
#define K3_PAIR(S)                                                               \
    {                                                                            \
        unsigned iv = __float_as_uint(S.w) & 31u;                                \
        float dxA = S.x - cA0, dyA = S.y - cA1, dzA = S.z - cA2;                 \
        float d2A = fmaf(dxA*dxA, eA0, fmaf(dyA*dyA, eA1, dzA*dzA*eA2));         \
        float dA = exp2f(fmaf(d2A, -1.44269504089f, 12.f));                      \
        bool gtA = (iv == idA);                                                  \
        int ubA = (int)dA; ubA = ubA > NB-1 ? NB-1 : ubA;                        \
        unsigned offA = gtA ? (unsigned)(2*NB - 1 - ubA) : (unsigned)ubA;        \
        atomicAdd(&shA[offA], 1u);                                              \
        if (gtA) { float df = S.w - dA * (1.f/4096.f); sacc += df * df; }        \
        float dxB = S.x - cB0, dyB = S.y - cB1, dzB = S.z - cB2;                 \
        float d2B = fmaf(dxB*dxB, eB0, fmaf(dyB*dyB, eB1, dzB*dzB*eB2));         \
        float dB = exp2f(fmaf(d2B, -1.44269504089f, 12.f));                      \
        bool gtB = (iv == idB);                                                  \
        int ubB = (int)dB; ubB = ubB > NB-1 ? NB-1 : ubB;                        \
        unsigned offB = gtB ? (unsigned)(2*NB - 1 - ubB) : (unsigned)ubB;        \
        atomicAdd(&shB[offB], 1u);                                              \
        if (gtB) { float df = S.w - dB * (1.f/4096.f); sacc += df * df; }        \
    }

__global__ void __launch_bounds__(512, 3) k3() {
    extern __shared__ unsigned sh[];     // 2 x 2*NB u32 = 64KB
    unsigned* shA = sh;
    unsigned* shB = sh + 2*NB;
    __shared__ float swr[16];

    int b = blockIdx.z, p = blockIdx.x, s = blockIdx.y;
    int biA = b * NID + 2*p, biB = biA + 1;
    unsigned idA = 2*p + 1, idB = 2*p + 2;
    if (g_cnt[biA] == 0.f && g_cnt[biB] == 0.f) return;

    float cA0 = g_center[biA][0], cA1 = g_center[biA][1], cA2 = g_center[biA][2];
    float eA0 = g_sexp[biA][0],   eA1 = g_sexp[biA][1],   eA2 = g_sexp[biA][2];
    float cB0 = g_center[biB][0], cB1 = g_center[biB][1], cB2 = g_center[biB][2];
    float eB0 = g_sexp[biB][0],   eB1 = g_sexp[biB][1],   eB2 = g_sexp[biB][2];

    int tid = threadIdx.x;
    for (int i = tid; i < 4*NB; i += 512) sh[i] = 0u;
    __syncthreads();

    const float4* __restrict__ se = g_se + (size_t)b * DHW;
    float sacc = 0.f;
    int v0 = s * CH;
    int vend = v0 + CH; if (vend > DHW) vend = DHW;

    int v = v0 + tid;
    for (; v + 512 < vend; v += 1024) {
        float4 S1 = se[v];
        float4 S2 = se[v + 512];
        K3_PAIR(S1)
        K3_PAIR(S2)
    }
    for (; v < vend; v += 512) {
        float4 S1 = se[v];
        K3_PAIR(S1)
    }

    // warp-reduce seed loss (both instances share batch b)
    for (int o = 16; o; o >>= 1) sacc += __shfl_down_sync(0xffffffffu, sacc, o);
    if ((tid & 31) == 0) swr[tid >> 5] = sacc;
    __syncthreads();
    if (tid == 0) {
        double ssum = 0.0;
        for (int i = 0; i < 16; i++) ssum += (double)swr[i];
        atomicAdd(&g_seedl[b], ssum);
    }
    // dump partial histograms (plain stores)
    for (int i = tid; i < 2*NB; i += 512) {
        g_h32[biA][s][i] = shA[i];
        g_h32[biB][s][i] = shB[i];
    }
}

// ---------------- pass 4: Lovasz via histogram scan ----------------
#define NT4 512
#define PER4 (NB / NT4)   // 8
__global__ void k4() {
    __shared__ float pc[NB], nc[NB];     // counts by ascending bin
    __shared__ float sp[NT4], sn[NT4];
    __shared__ double sctr[NT4];

    int bi = blockIdx.x, b = bi / NID;
    float G = g_cnt[bi];
    if (G == 0.f) return;
    int t = threadIdx.x;

    // phase 1: coalesced gather of per-slice counts
    #pragma unroll
    for (int i = 0; i < PER4; i++) {
        int j = i * NT4 + t;             // ascending bin index, coalesced
        unsigned cp = 0, cn_ = 0;
        #pragma unroll
        for (int s = 0; s < SLICES; s++) {
            cp  += g_h32[bi][s][NB + j];
            cn_ += g_h32[bi][s][j];
        }
        pc[j] = (float)cp;
        nc[j] = (float)cn_;
    }
    __syncthreads();

    // phase 2: thread t owns descending positions [t*PER4, t*PER4+PER4)
    float tp = 0.f, tn = 0.f;
    #pragma unroll
    for (int i = 0; i < PER4; i++) {
        int j = NB - 1 - (t * PER4 + i);
        tp += pc[j]; tn += nc[j];
    }
    sp[t] = tp; sn[t] = tn;
    __syncthreads();
    for (int o = 1; o < NT4; o <<= 1) {
        float ap = (t >= o) ? sp[t - o] : 0.f;
        float an = (t >= o) ? sn[t - o] : 0.f;
        __syncthreads();
        sp[t] += ap; sn[t] += an;
        __syncthreads();
    }
    float P = sp[t] - tp;   // exclusive cumulative positives before this thread's bins
    float N = sn[t] - tn;

    double contrib = 0.0;
    #pragma unroll
    for (int i = 0; i < PER4; i++) {
        int j = NB - 1 - (t * PER4 + i);
        float p = pc[j], n = nc[j];
        double ec = ((double)j + 0.5) * (1.0/2048.0);   // bin-center error value
        double U0 = (double)G + (double)N;
        double U1 = U0 + (double)n;
        // average of pos-first and neg-first within-bin orderings:
        if (p > 0.f) contrib += (double)p * ec * 0.5 * (1.0/U0 + 1.0/U1);
        if (n > 0.f) contrib += (double)n * ec *
                                ((double)G - (double)P - 0.5*(double)p) / (U0 * U1);
        P += p; N += n;
    }
    sctr[t] = contrib;
    __syncthreads();
    for (int o = NT4/2; o > 0; o >>= 1) {
        if (t < o) sctr[t] += sctr[t + o];
        __syncthreads();
    }
    if (t == 0) atomicAdd(&g_instl[b], sctr[0]);
}

// ---------------- pass 5: final reduction ----------------
__global__ void k5(float* __restrict__ out) {
    double li = 0.0, lv = 0.0, ls = 0.0;
    for (int b = 0; b < BN; b++) {
        li += g_instl[b] / (double)g_denom[b];
        lv += (double)g_varsum[b] / (double)g_denom[b];
        ls += (g_seedl[b] + g_bg[b]) / (double)DHW;
    }
    li /= (double)BN;
    lv = lv * 10.0 / (double)BN;   // W_VAR = 10
    ls /= (double)BN;
    out[0] = (float)li;
    out[1] = (float)lv;
    out[2] = (float)ls;
    out[3] = (float)(li + lv + ls);
}

// ---------------- launch ----------------
extern "C" void kernel_launch(void* const* d_in, const int* in_sizes, int n_in,
                              void* d_out, int out_size) {
    const float* pred = (const float*)d_in[0];
    const int*   inst = (const int*)d_in[1];
    const int*   lab  = (const int*)d_in[2];
    // d_in[3] = center_images (unused), d_in[4] = xyzm (computed analytically)

    cudaFuncSetAttribute(k3, cudaFuncAttributeMaxDynamicSharedMemorySize, 4*NB*4);

    kzero<<<1, 640>>>();
    k1<<<dim3(288, BN), 256>>>(pred, inst, lab);
    k2<<<1, 64>>>();
    k3<<<dim3(NPAIR, SLICES, BN), 512, 4*NB*4>>>();
    k4<<<NBI, NT4>>>();
    k5<<<1, 1>>>((float*)d_out);
}

// round 10
// speedup vs baseline: 7.5248x; 1.0668x over previous
#include <cuda_runtime.h>
#include <math.h>

// Problem constants (fixed shapes)
#define DN 32
#define HN 192
#define WN 192
#define DHW (DN*HN*WN)      // 1179648
#define BN 4
#define CN 7
#define NID 16
#define NBI (BN*NID)        // 64
#define NB 4096             // histogram bins over e in [0,2]
#define SLICES 13
#define CH ((DHW + SLICES - 1) / SLICES)   // 90743
#define NPAIR (NID/2)       // 8 id-pairs per batch

typedef unsigned long long ull;

// ---------------- device scratch (static; no allocations) ----------------
__device__ float4 g_se[(size_t)BN*DHW];             // tanh(pred[:3])+xyzm, seed(+id in low mantissa)
__device__ unsigned g_h32[NBI][SLICES][2*NB];       // per-slice count histograms (27MB)
__device__ double g_acc[NBI][10];                   // cnt, sum_xyz, sum(sig+16), sum sig^2
__device__ double g_bg[BN];
__device__ double g_seedl[BN];
__device__ double g_instl[BN];
__device__ float  g_center[NBI][3];
__device__ float  g_sexp[NBI][3];
__device__ float  g_cnt[NBI];
__device__ float  g_varsum[BN];
__device__ float  g_denom[BN];

// ---------------- zero the small accumulators only ----------------
__global__ void kzero() {
    int t = threadIdx.x;
    double* acc = &g_acc[0][0];
    if (t < NBI*10) acc[t] = 0.0;
    if (t < BN) { g_bg[t] = 0.0; g_seedl[t] = 0.0; g_instl[t] = 0.0; }
}

__device__ __forceinline__ float fast_tanh(float x) {
    return 1.f - __fdividef(2.f, 1.f + __expf(2.f * x));
}

// ---------------- pass 1: preprocess + per-instance accumulators ----------------
// 3 packed u64 atomics per fg voxel, per-warp replica banks:
//  w0: cnt[0:10) | zi[10:24) | yi[24:41) | xi[41:58)          (exact integers)
//  w1: (s0+16)*128 [0:21) | (s1+16)*128 [21:42) | (s2+16)*128 [42:63)
//  w2: s0^2*32 [0:21)     | s1^2*32 [21:42)     | s2^2*32 [42:63)
#define VOX(p0,p1,p2,s0,s1,s2,p6, idv, lbv, xmv, xiv, vi)                        \
    {                                                                            \
        float e0 = fast_tanh(p0) + (xmv);                                        \
        float e1 = fast_tanh(p1) + ym;                                           \
        float e2 = fast_tanh(p2) + zm;                                           \
        float seed = __fdividef(1.f, 1.f + __expf(-(p6)));                       \
        unsigned wb = (__float_as_uint(seed) & ~31u) | (unsigned)(idv);          \
        o4[vi] = make_float4(e0, e1, e2, __uint_as_float(wb));                   \
        if ((idv) > 0) {                                                         \
            ull* s = &my[((idv)-1)*3];                                           \
            ull w0 = 1ULL | ((ull)zi << 10) | ((ull)yi << 24) | ((ull)(xiv) << 41); \
            ull w1 = (ull)__float2uint_rn(fmaf(s0,128.f,2048.f))                 \
                   | ((ull)__float2uint_rn(fmaf(s1,128.f,2048.f)) << 21)         \
                   | ((ull)__float2uint_rn(fmaf(s2,128.f,2048.f)) << 42);        \
            ull w2 = (ull)__float2uint_rn((s0)*(s0)*32.f)                        \
                   | ((ull)__float2uint_rn((s1)*(s1)*32.f) << 21)                \
                   | ((ull)__float2uint_rn((s2)*(s2)*32.f) << 42);               \
            atomicAdd(&s[0], w0);                                                \
            atomicAdd(&s[1], w1);                                                \
            atomicAdd(&s[2], w2);                                                \
        }                                                                        \
        if ((lbv) == 0) bgl += seed * seed;                                      \
    }

__global__ void __launch_bounds__(256) k1(const float* __restrict__ pred,
                                          const int* __restrict__ inst,
                                          const int* __restrict__ lab) {
    __shared__ ull sacc[8][NID*3];   // one replica per warp (3KB)
    __shared__ float swr[8];
    int tid = threadIdx.x;
    for (int i = tid; i < 8*NID*3; i += 256) (&sacc[0][0])[i] = 0ULL;
    __syncthreads();
    ull* my = sacc[tid >> 5];

    int b = blockIdx.y;
    const float4* __restrict__ p4 = (const float4*)(pred + (size_t)b * CN * DHW);
    const int4*   __restrict__ i4 = (const int4*)(inst + (size_t)b * DHW);
    const int4*   __restrict__ l4 = (const int4*)(lab  + (size_t)b * DHW);
    float4* o4 = g_se + (size_t)b * DHW;
    float bgl = 0.f;
    const int Q = DHW / 4;

    for (int q = blockIdx.x * 256 + tid; q < Q; q += gridDim.x * 256) {
        float4 P0 = p4[q],       P1 = p4[Q+q],   P2 = p4[2*Q+q];
        float4 S0 = p4[3*Q+q],   S1 = p4[4*Q+q], S2 = p4[5*Q+q];
        float4 P6 = p4[6*Q+q];
        int4 ID = i4[q];
        int4 LB = l4[q];
        int v = q * 4;
        int x0 = v % WN;
        int r  = v / WN;
        int yi = r % HN, zi = r / HN;
        float ym = (float)yi * (1.f/(HN-1));
        float zm = (float)zi * (1.f/(DN-1));
        float xm = (float)x0 * (1.f/(WN-1));
        VOX(P0.x, P1.x, P2.x, S0.x, S1.x, S2.x, P6.x, ID.x, LB.x, xm,              x0,   v+0)
        VOX(P0.y, P1.y, P2.y, S0.y, S1.y, S2.y, P6.y, ID.y, LB.y, xm + 1.f/(WN-1), x0+1, v+1)
        VOX(P0.z, P1.z, P2.z, S0.z, S1.z, S2.z, P6.z, ID.z, LB.z, xm + 2.f/(WN-1), x0+2, v+2)
        VOX(P0.w, P1.w, P2.w, S0.w, S1.w, S2.w, P6.w, ID.w, LB.w, xm + 3.f/(WN-1), x0+3, v+3)
    }
    // warp-reduce bg
    for (int o = 16; o; o >>= 1) bgl += __shfl_down_sync(0xffffffffu, bgl, o);
    if ((tid & 31) == 0) swr[tid >> 5] = bgl;
    __syncthreads();
    if (tid == 0) {
        double s = 0.0;
        for (int i = 0; i < 8; i++) s += (double)swr[i];
        atomicAdd(&g_bg[b], s);
    }
    // decode fields per replica, sum, merge to global (48 threads: id x word)
    if (tid < NID*3) {
        int id = tid / 3, w = tid % 3;
        double* g = g_acc[b*NID + id];
        if (w == 0) {
            ull cnt = 0, sxi = 0, syi = 0, szi = 0;
            #pragma unroll
            for (int rp = 0; rp < 8; rp++) {
                ull v = sacc[rp][id*3];
                cnt += v & 1023ULL;
                szi += (v >> 10) & 0x3FFFULL;
                syi += (v >> 24) & 0x1FFFFULL;
                sxi += (v >> 41);
            }
            if (cnt) {
                atomicAdd(&g[0], (double)cnt);
                atomicAdd(&g[1], (double)sxi * (1.0/(WN-1)));
                atomicAdd(&g[2], (double)syi * (1.0/(HN-1)));
                atomicAdd(&g[3], (double)szi * (1.0/(DN-1)));
            }
        } else {
            ull f0 = 0, f1 = 0, f2 = 0;
            #pragma unroll
            for (int rp = 0; rp < 8; rp++) {
                ull v = sacc[rp][id*3 + w];
                f0 += v & 0x1FFFFFULL;
                f1 += (v >> 21) & 0x1FFFFFULL;
                f2 += (v >> 42);
            }
            if (f0 | f1 | f2) {
                double sc = (w == 1) ? (1.0/128.0) : (1.0/32.0);
                int base = (w == 1) ? 4 : 7;
                atomicAdd(&g[base+0], (double)f0 * sc);
                atomicAdd(&g[base+1], (double)f1 * sc);
                atomicAdd(&g[base+2], (double)f2 * sc);
            }
        }
    }
}

// ---------------- pass 2: per-instance stats ----------------
// g_acc[4..6] hold sum(sigma+16): subtract 16*cnt here
__global__ void k2() {
    __shared__ float sobj[BN], svar[BN];
    int t = threadIdx.x;            // 0..63  (b*16 + (id-1))
    if (t < BN) { sobj[t] = 0.f; svar[t] = 0.f; }
    __syncthreads();
    int b = t / NID;

    double cnt = g_acc[t][0];
    bool ex = cnt > 0.0;
    double safe = cnt > 1.0 ? cnt : 1.0;
    double c0 = g_acc[t][1] / safe, c1 = g_acc[t][2] / safe, c2 = g_acc[t][3] / safe;
    double m0 = (g_acc[t][4] - 16.0*cnt) / safe;
    double m1 = (g_acc[t][5] - 16.0*cnt) / safe;
    double m2 = (g_acc[t][6] - 16.0*cnt) / safe;
    double var = 0.0;
    if (ex) {
        var = ((g_acc[t][7] - cnt*m0*m0) +
               (g_acc[t][8] - cnt*m1*m1) +
               (g_acc[t][9] - cnt*m2*m2)) / (3.0 * safe);
    }
    g_center[t][0] = (float)c0; g_center[t][1] = (float)c1; g_center[t][2] = (float)c2;
    g_sexp[t][0] = expf((float)(m0 * 10.0));
    g_sexp[t][1] = expf((float)(m1 * 10.0));
    g_sexp[t][2] = expf((float)(m2 * 10.0));
    g_cnt[t] = ex ? (float)cnt : 0.f;

    atomicAdd(&sobj[b], ex ? 1.f : 0.f);
    atomicAdd(&svar[b], (float)var);
    __syncthreads();
    if (t < BN) {
        g_denom[t]  = sobj[t] > 1.f ? sobj[t] : 1.f;
        g_varsum[t] = svar[t];
    }
}

// ---------------- pass 3: per-(b,idpair,slice) count histograms + seed loss ----------------
#define K3_PAIR(S)                                                               \
    {                                                                            \
        unsigned iv = __float_as_uint(S.w) & 31u;                                \
        float dxA = S.x - cA0, dyA = S.y - cA1, dzA = S.z - cA2;                 \
        float d2A = fmaf(dxA*dxA, eA0, fmaf(dyA*dyA, eA1, dzA*dzA*eA2));         \
        float dA = exp2f(fmaf(d2A, -1.44269504089f, 12.f));                      \
        bool gtA = (iv == idA);                                                  \
        int ubA = (int)dA; ubA = ubA > NB-1 ? NB-1 : ubA;                        \
        unsigned offA = gtA ? (unsigned)(2*NB - 1 - ubA) : (unsigned)ubA;        \
        atomicAdd(&shA[offA], 1u);                                              \
        if (gtA) { float df = S.w - dA * (1.f/4096.f); sacc += df * df; }        \
        float dxB = S.x - cB0, dyB = S.y - cB1, dzB = S.z - cB2;                 \
        float d2B = fmaf(dxB*dxB, eB0, fmaf(dyB*dyB, eB1, dzB*dzB*eB2));         \
        float dB = exp2f(fmaf(d2B, -1.44269504089f, 12.f));                      \
        bool gtB = (iv == idB);                                                  \
        int ubB = (int)dB; ubB = ubB > NB-1 ? NB-1 : ubB;                        \
        unsigned offB = gtB ? (unsigned)(2*NB - 1 - ubB) : (unsigned)ubB;        \
        atomicAdd(&shB[offB], 1u);                                              \
        if (gtB) { float df = S.w - dB * (1.f/4096.f); sacc += df * df; }        \
    }

__global__ void __launch_bounds__(512, 3) k3() {
    extern __shared__ unsigned sh[];     // 2 x 2*NB u32 = 64KB
    unsigned* shA = sh;
    unsigned* shB = sh + 2*NB;
    __shared__ float swr[16];

    int b = blockIdx.z, p = blockIdx.x, s = blockIdx.y;
    int biA = b * NID + 2*p, biB = biA + 1;
    unsigned idA = 2*p + 1, idB = 2*p + 2;
    if (g_cnt[biA] == 0.f && g_cnt[biB] == 0.f) return;

    float cA0 = g_center[biA][0], cA1 = g_center[biA][1], cA2 = g_center[biA][2];
    float eA0 = g_sexp[biA][0],   eA1 = g_sexp[biA][1],   eA2 = g_sexp[biA][2];
    float cB0 = g_center[biB][0], cB1 = g_center[biB][1], cB2 = g_center[biB][2];
    float eB0 = g_sexp[biB][0],   eB1 = g_sexp[biB][1],   eB2 = g_sexp[biB][2];

    int tid = threadIdx.x;
    for (int i = tid; i < 4*NB; i += 512) sh[i] = 0u;
    __syncthreads();

    const float4* __restrict__ se = g_se + (size_t)b * DHW;
    float sacc = 0.f;
    int v0 = s * CH;
    int vend = v0 + CH; if (vend > DHW) vend = DHW;

    int v = v0 + tid;
    for (; v + 512 < vend; v += 1024) {
        float4 S1 = se[v];
        float4 S2 = se[v + 512];
        K3_PAIR(S1)
        K3_PAIR(S2)
    }
    for (; v < vend; v += 512) {
        float4 S1 = se[v];
        K3_PAIR(S1)
    }

    // warp-reduce seed loss (both instances share batch b)
    for (int o = 16; o; o >>= 1) sacc += __shfl_down_sync(0xffffffffu, sacc, o);
    if ((tid & 31) == 0) swr[tid >> 5] = sacc;
    __syncthreads();
    if (tid == 0) {
        double ssum = 0.0;
        for (int i = 0; i < 16; i++) ssum += (double)swr[i];
        atomicAdd(&g_seedl[b], ssum);
    }
    // dump partial histograms (plain stores)
    for (int i = tid; i < 2*NB; i += 512) {
        g_h32[biA][s][i] = shA[i];
        g_h32[biB][s][i] = shB[i];
    }
}

// ---------------- pass 4: Lovasz via histogram scan ----------------
#define NT4 512
#define PER4 (NB / NT4)   // 8
__global__ void k4() {
    __shared__ float pc[NB], nc[NB];     // counts by ascending bin
    __shared__ float sp[NT4], sn[NT4];
    __shared__ double sctr[NT4];

    int bi = blockIdx.x, b = bi / NID;
    float G = g_cnt[bi];
    if (G == 0.f) return;
    int t = threadIdx.x;

    // phase 1: coalesced gather of per-slice counts
    #pragma unroll
    for (int i = 0; i < PER4; i++) {
        int j = i * NT4 + t;             // ascending bin index, coalesced
        unsigned cp = 0, cn_ = 0;
        #pragma unroll
        for (int s = 0; s < SLICES; s++) {
            cp  += g_h32[bi][s][NB + j];
            cn_ += g_h32[bi][s][j];
        }
        pc[j] = (float)cp;
        nc[j] = (float)cn_;
    }
    __syncthreads();

    // phase 2: thread t owns descending positions [t*PER4, t*PER4+PER4)
    float tp = 0.f, tn = 0.f;
    #pragma unroll
    for (int i = 0; i < PER4; i++) {
        int j = NB - 1 - (t * PER4 + i);
        tp += pc[j]; tn += nc[j];
    }
    sp[t] = tp; sn[t] = tn;
    __syncthreads();
    for (int o = 1; o < NT4; o <<= 1) {
        float ap = (t >= o) ? sp[t - o] : 0.f;
        float an = (t >= o) ? sn[t - o] : 0.f;
        __syncthreads();
        sp[t] += ap; sn[t] += an;
        __syncthreads();
    }
    float P = sp[t] - tp;   // exclusive cumulative positives before this thread's bins
    float N = sn[t] - tn;

    double contrib = 0.0;
    #pragma unroll
    for (int i = 0; i < PER4; i++) {
        int j = NB - 1 - (t * PER4 + i);
        float p = pc[j], n = nc[j];
        double ec = ((double)j + 0.5) * (1.0/2048.0);   // bin-center error value
        double U0 = (double)G + (double)N;
        double U1 = U0 + (double)n;
        // average of pos-first and neg-first within-bin orderings:
        if (p > 0.f) contrib += (double)p * ec * 0.5 * (1.0/U0 + 1.0/U1);
        if (n > 0.f) contrib += (double)n * ec *
                                ((double)G - (double)P - 0.5*(double)p) / (U0 * U1);
        P += p; N += n;
    }
    sctr[t] = contrib;
    __syncthreads();
    for (int o = NT4/2; o > 0; o >>= 1) {
        if (t < o) sctr[t] += sctr[t + o];
        __syncthreads();
    }
    if (t == 0) atomicAdd(&g_instl[b], sctr[0]);
}

// ---------------- pass 5: final reduction ----------------
__global__ void k5(float* __restrict__ out) {
    double li = 0.0, lv = 0.0, ls = 0.0;
    for (int b = 0; b < BN; b++) {
        li += g_instl[b] / (double)g_denom[b];
        lv += (double)g_varsum[b] / (double)g_denom[b];
        ls += (g_seedl[b] + g_bg[b]) / (double)DHW;
    }
    li /= (double)BN;
    lv = lv * 10.0 / (double)BN;   // W_VAR = 10
    ls /= (double)BN;
    out[0] = (float)li;
    out[1] = (float)lv;
    out[2] = (float)ls;
    out[3] = (float)(li + lv + ls);
}

// ---------------- launch ----------------
extern "C" void kernel_launch(void* const* d_in, const int* in_sizes, int n_in,
                              void* d_out, int out_size) {
    const float* pred = (const float*)d_in[0];
    const int*   inst = (const int*)d_in[1];
    const int*   lab  = (const int*)d_in[2];
    // d_in[3] = center_images (unused), d_in[4] = xyzm (computed analytically)

    cudaFuncSetAttribute(k3, cudaFuncAttributeMaxDynamicSharedMemorySize, 4*NB*4);

    kzero<<<1, 640>>>();
    k1<<<dim3(288, BN), 256>>>(pred, inst, lab);
    k2<<<1, 64>>>();
    k3<<<dim3(NPAIR, SLICES, BN), 512, 4*NB*4>>>();
    k4<<<NBI, NT4>>>();
    k5<<<1, 1>>>((float*)d_out);
}

// round 11
// speedup vs baseline: 7.8699x; 1.0459x over previous
#include <cuda_runtime.h>
#include <math.h>

// Problem constants (fixed shapes)
#define DN 32
#define HN 192
#define WN 192
#define DHW (DN*HN*WN)      // 1179648
#define BN 4
#define CN 7
#define NID 16
#define NBI (BN*NID)        // 64
#define NB 4096             // histogram bins over e in [0,2]
#define SLICES 13
#define CH ((DHW + SLICES - 1) / SLICES)   // 90743
#define NPAIR (NID/2)       // 8 id-pairs per batch

typedef unsigned long long ull;

// ---------------- device scratch (static; no allocations) ----------------
__device__ float4 g_se[(size_t)BN*DHW];             // tanh(pred[:3])+xyzm, seed(+id in low mantissa)
__device__ unsigned g_hcnt[NBI][2*NB];              // merged count histograms (2MB)
__device__ double g_acc[NBI][10];                   // cnt, sum_xyz, sum(sig+16), sum sig^2
__device__ double g_bg[BN];
__device__ double g_seedl[BN];
__device__ double g_instl[BN];
__device__ float  g_center[NBI][3];
__device__ float  g_sexp[NBI][3];
__device__ float  g_cnt[NBI];
__device__ float  g_varsum[BN];
__device__ float  g_denom[BN];

// ---------------- zero histograms + small accumulators ----------------
__global__ void kzero() {
    int t = blockIdx.x * blockDim.x + threadIdx.x;
    int stride = gridDim.x * blockDim.x;
    unsigned* hc = &g_hcnt[0][0];
    for (int i = t; i < NBI*2*NB; i += stride) hc[i] = 0u;
    if (t < NBI*10) (&g_acc[0][0])[t] = 0.0;
    if (t < BN) { g_bg[t] = 0.0; g_seedl[t] = 0.0; g_instl[t] = 0.0; }
}

__device__ __forceinline__ float fast_tanh(float x) {
    return 1.f - __fdividef(2.f, 1.f + __expf(2.f * x));
}

// ---------------- pass 1: preprocess + per-instance accumulators ----------------
// 3 packed u64 words per fg voxel, merged across the 4-voxel quad by id before
// hitting per-warp replica banks:
//  w0: cnt[0:10) | zi[10:24) | yi[24:41) | xi[41:58)          (exact integers)
//  w1: (s0+16)*128 [0:21) | (s1+16)*128 [21:42) | (s2+16)*128 [42:63)
//  w2: s0^2*32 [0:21)     | s1^2*32 [21:42)     | s2^2*32 [42:63)
#define VOXN(i, p0,p1,p2,s0,s1,s2,p6, lbv, xmv, xiv, vi)                         \
    {                                                                            \
        float e0 = fast_tanh(p0) + (xmv);                                        \
        float e1 = fast_tanh(p1) + ym;                                           \
        float e2 = fast_tanh(p2) + zm;                                           \
        float seed = __fdividef(1.f, 1.f + __expf(-(p6)));                       \
        unsigned wb = (__float_as_uint(seed) & ~31u) | (unsigned)ids[i];         \
        o4[vi] = make_float4(e0, e1, e2, __uint_as_float(wb));                   \
        W0[i] = 1ULL | ((ull)zi << 10) | ((ull)yi << 24) | ((ull)(xiv) << 41);   \
        W1[i] = (ull)__float2uint_rn(fmaf(s0,128.f,2048.f))                      \
              | ((ull)__float2uint_rn(fmaf(s1,128.f,2048.f)) << 21)              \
              | ((ull)__float2uint_rn(fmaf(s2,128.f,2048.f)) << 42);             \
        W2[i] = (ull)__float2uint_rn((s0)*(s0)*32.f)                             \
              | ((ull)__float2uint_rn((s1)*(s1)*32.f) << 21)                     \
              | ((ull)__float2uint_rn((s2)*(s2)*32.f) << 42);                    \
        if ((lbv) == 0) bgl += seed * seed;                                      \
    }

__global__ void __launch_bounds__(256) k1(const float* __restrict__ pred,
                                          const int* __restrict__ inst,
                                          const int* __restrict__ lab) {
    __shared__ ull sacc[8][NID*3];   // one replica per warp (3KB)
    __shared__ float swr[8];
    int tid = threadIdx.x;
    for (int i = tid; i < 8*NID*3; i += 256) (&sacc[0][0])[i] = 0ULL;
    __syncthreads();
    ull* my = sacc[tid >> 5];

    int b = blockIdx.y;
    const float4* __restrict__ p4 = (const float4*)(pred + (size_t)b * CN * DHW);
    const int4*   __restrict__ i4 = (const int4*)(inst + (size_t)b * DHW);
    const int4*   __restrict__ l4 = (const int4*)(lab  + (size_t)b * DHW);
    float4* o4 = g_se + (size_t)b * DHW;
    float bgl = 0.f;
    const int Q = DHW / 4;

    for (int q = blockIdx.x * 256 + tid; q < Q; q += gridDim.x * 256) {
        float4 P0 = p4[q],       P1 = p4[Q+q],   P2 = p4[2*Q+q];
        float4 S0 = p4[3*Q+q],   S1 = p4[4*Q+q], S2 = p4[5*Q+q];
        float4 P6 = p4[6*Q+q];
        int4 ID = i4[q];
        int4 LB = l4[q];
        int v = q * 4;
        int x0 = v % WN;
        int r  = v / WN;
        int yi = r % HN, zi = r / HN;
        float ym = (float)yi * (1.f/(HN-1));
        float zm = (float)zi * (1.f/(DN-1));
        float xm = (float)x0 * (1.f/(WN-1));

        int ids[4] = {ID.x, ID.y, ID.z, ID.w};
        ull W0[4], W1[4], W2[4];
        VOXN(0, P0.x, P1.x, P2.x, S0.x, S1.x, S2.x, P6.x, LB.x, xm,              x0,   v+0)
        VOXN(1, P0.y, P1.y, P2.y, S0.y, S1.y, S2.y, P6.y, LB.y, xm + 1.f/(WN-1), x0+1, v+1)
        VOXN(2, P0.z, P1.z, P2.z, S0.z, S1.z, S2.z, P6.z, LB.z, xm + 2.f/(WN-1), x0+2, v+2)
        VOXN(3, P0.w, P1.w, P2.w, S0.w, S1.w, S2.w, P6.w, LB.w, xm + 3.f/(WN-1), x0+3, v+3)

        // merge same-id voxels within the quad, then one atomic triple per id
        #pragma unroll
        for (int i = 0; i < 4; i++) {
            int idv = ids[i];
            if (idv > 0) {
                ull a0 = W0[i], a1 = W1[i], a2 = W2[i];
                #pragma unroll
                for (int j = i + 1; j < 4; j++) {
                    if (ids[j] == idv) { a0 += W0[j]; a1 += W1[j]; a2 += W2[j]; ids[j] = 0; }
                }
                ull* s = &my[(idv-1)*3];
                atomicAdd(&s[0], a0);
                atomicAdd(&s[1], a1);
                atomicAdd(&s[2], a2);
            }
        }
    }
    // warp-reduce bg
    for (int o = 16; o; o >>= 1) bgl += __shfl_down_sync(0xffffffffu, bgl, o);
    if ((tid & 31) == 0) swr[tid >> 5] = bgl;
    __syncthreads();
    if (tid == 0) {
        double s = 0.0;
        for (int i = 0; i < 8; i++) s += (double)swr[i];
        atomicAdd(&g_bg[b], s);
    }
    // decode fields per replica, sum, merge to global (48 threads: id x word)
    if (tid < NID*3) {
        int id = tid / 3, w = tid % 3;
        double* g = g_acc[b*NID + id];
        if (w == 0) {
            ull cnt = 0, sxi = 0, syi = 0, szi = 0;
            #pragma unroll
            for (int rp = 0; rp < 8; rp++) {
                ull v = sacc[rp][id*3];
                cnt += v & 1023ULL;
                szi += (v >> 10) & 0x3FFFULL;
                syi += (v >> 24) & 0x1FFFFULL;
                sxi += (v >> 41);
            }
            if (cnt) {
                atomicAdd(&g[0], (double)cnt);
                atomicAdd(&g[1], (double)sxi * (1.0/(WN-1)));
                atomicAdd(&g[2], (double)syi * (1.0/(HN-1)));
                atomicAdd(&g[3], (double)szi * (1.0/(DN-1)));
            }
        } else {
            ull f0 = 0, f1 = 0, f2 = 0;
            #pragma unroll
            for (int rp = 0; rp < 8; rp++) {
                ull v = sacc[rp][id*3 + w];
                f0 += v & 0x1FFFFFULL;
                f1 += (v >> 21) & 0x1FFFFFULL;
                f2 += (v >> 42);
            }
            if (f0 | f1 | f2) {
                double sc = (w == 1) ? (1.0/128.0) : (1.0/32.0);
                int base = (w == 1) ? 4 : 7;
                atomicAdd(&g[base+0], (double)f0 * sc);
                atomicAdd(&g[base+1], (double)f1 * sc);
                atomicAdd(&g[base+2], (double)f2 * sc);
            }
        }
    }
}

// ---------------- pass 2: per-instance stats ----------------
// g_acc[4..6] hold sum(sigma+16): subtract 16*cnt here
__global__ void k2() {
    __shared__ float sobj[BN], svar[BN];
    int t = threadIdx.x;            // 0..63  (b*16 + (id-1))
    if (t < BN) { sobj[t] = 0.f; svar[t] = 0.f; }
    __syncthreads();
    int b = t / NID;

    double cnt = g_acc[t][0];
    bool ex = cnt > 0.0;
    double safe = cnt > 1.0 ? cnt : 1.0;
    double c0 = g_acc[t][1] / safe, c1 = g_acc[t][2] / safe, c2 = g_acc[t][3] / safe;
    double m0 = (g_acc[t][4] - 16.0*cnt) / safe;
    double m1 = (g_acc[t][5] - 16.0*cnt) / safe;
    double m2 = (g_acc[t][6] - 16.0*cnt) / safe;
    double var = 0.0;
    if (ex) {
        var = ((g_acc[t][7] - cnt*m0*m0) +
               (g_acc[t][8] - cnt*m1*m1) +
               (g_acc[t][9] - cnt*m2*m2)) / (3.0 * safe);
    }
    g_center[t][0] = (float)c0; g_center[t][1] = (float)c1; g_center[t][2] = (float)c2;
    g_sexp[t][0] = expf((float)(m0 * 10.0));
    g_sexp[t][1] = expf((float)(m1 * 10.0));
    g_sexp[t][2] = expf((float)(m2 * 10.0));
    g_cnt[t] = ex ? (float)cnt : 0.f;

    atomicAdd(&sobj[b], ex ? 1.f : 0.f);
    atomicAdd(&svar[b], (float)var);
    __syncthreads();
    if (t < BN) {
        g_denom[t]  = sobj[t] > 1.f ? sobj[t] : 1.f;
        g_varsum[t] = svar[t];
    }
}

// ---------------- pass 3: per-(b,idpair,slice) count histograms + seed loss ----------------
#define K3_PAIR(S)                                                               \
    {                                                                            \
        unsigned iv = __float_as_uint(S.w) & 31u;                                \
        float dxA = S.x - cA0, dyA = S.y - cA1, dzA = S.z - cA2;                 \
        float d2A = fmaf(dxA*dxA, eA0, fmaf(dyA*dyA, eA1, dzA*dzA*eA2));         \
        float dA = exp2f(fmaf(d2A, -1.44269504089f, 12.f));                      \
        bool gtA = (iv == idA);                                                  \
        int ubA = (int)dA; ubA = ubA > NB-1 ? NB-1 : ubA;                        \
        unsigned offA = gtA ? (unsigned)(2*NB - 1 - ubA) : (unsigned)ubA;        \
        atomicAdd(&shA[offA], 1u);                                              \
        if (gtA) { float df = S.w - dA * (1.f/4096.f); sacc += df * df; }        \
        float dxB = S.x - cB0, dyB = S.y - cB1, dzB = S.z - cB2;                 \
        float d2B = fmaf(dxB*dxB, eB0, fmaf(dyB*dyB, eB1, dzB*dzB*eB2));         \
        float dB = exp2f(fmaf(d2B, -1.44269504089f, 12.f));                      \
        bool gtB = (iv == idB);                                                  \
        int ubB = (int)dB; ubB = ubB > NB-1 ? NB-1 : ubB;                        \
        unsigned offB = gtB ? (unsigned)(2*NB - 1 - ubB) : (unsigned)ubB;        \
        atomicAdd(&shB[offB], 1u);                                              \
        if (gtB) { float df = S.w - dB * (1.f/4096.f); sacc += df * df; }        \
    }

__global__ void __launch_bounds__(512, 3) k3() {
    extern __shared__ unsigned sh[];     // 2 x 2*NB u32 = 64KB
    unsigned* shA = sh;
    unsigned* shB = sh + 2*NB;
    __shared__ float swr[16];

    int b = blockIdx.z, p = blockIdx.x, s = blockIdx.y;
    int biA = b * NID + 2*p, biB = biA + 1;
    unsigned idA = 2*p + 1, idB = 2*p + 2;
    if (g_cnt[biA] == 0.f && g_cnt[biB] == 0.f) return;

    float cA0 = g_center[biA][0], cA1 = g_center[biA][1], cA2 = g_center[biA][2];
    float eA0 = g_sexp[biA][0],   eA1 = g_sexp[biA][1],   eA2 = g_sexp[biA][2];
    float cB0 = g_center[biB][0], cB1 = g_center[biB][1], cB2 = g_center[biB][2];
    float eB0 = g_sexp[biB][0],   eB1 = g_sexp[biB][1],   eB2 = g_sexp[biB][2];

    int tid = threadIdx.x;
    for (int i = tid; i < 4*NB; i += 512) sh[i] = 0u;
    __syncthreads();

    const float4* __restrict__ se = g_se + (size_t)b * DHW;
    float sacc = 0.f;
    int v0 = s * CH;
    int vend = v0 + CH; if (vend > DHW) vend = DHW;

    int v = v0 + tid;
    for (; v + 512 < vend; v += 1024) {
        float4 S1 = se[v];
        float4 S2 = se[v + 512];
        K3_PAIR(S1)
        K3_PAIR(S2)
    }
    for (; v < vend; v += 512) {
        float4 S1 = se[v];
        K3_PAIR(S1)
    }

    // warp-reduce seed loss (both instances share batch b)
    for (int o = 16; o; o >>= 1) sacc += __shfl_down_sync(0xffffffffu, sacc, o);
    if ((tid & 31) == 0) swr[tid >> 5] = sacc;
    __syncthreads();
    if (tid == 0) {
        double ssum = 0.0;
        for (int i = 0; i < 16; i++) ssum += (double)swr[i];
        atomicAdd(&g_seedl[b], ssum);
    }
    // sparse merge into single global histogram (RED, no return; deterministic)
    for (int i = tid; i < 2*NB; i += 512) {
        unsigned cA = shA[i];
        unsigned cB = shB[i];
        if (cA) atomicAdd(&g_hcnt[biA][i], cA);
        if (cB) atomicAdd(&g_hcnt[biB][i], cB);
    }
}

// ---------------- pass 4: Lovasz via histogram scan ----------------
#define NT4 512
#define PER4 (NB / NT4)   // 8
__global__ void k4() {
    __shared__ float pc[NB], nc[NB];     // counts by ascending bin
    __shared__ float sp[NT4], sn[NT4];
    __shared__ double sctr[NT4];

    int bi = blockIdx.x, b = bi / NID;
    float G = g_cnt[bi];
    if (G == 0.f) return;
    int t = threadIdx.x;

    // phase 1: coalesced gather of merged counts
    #pragma unroll
    for (int i = 0; i < PER4; i++) {
        int j = i * NT4 + t;             // ascending bin index, coalesced
        pc[j] = (float)g_hcnt[bi][NB + j];
        nc[j] = (float)g_hcnt[bi][j];
    }
    __syncthreads();

    // phase 2: thread t owns descending positions [t*PER4, t*PER4+PER4)
    float tp = 0.f, tn = 0.f;
    #pragma unroll
    for (int i = 0; i < PER4; i++) {
        int j = NB - 1 - (t * PER4 + i);
        tp += pc[j]; tn += nc[j];
    }
    sp[t] = tp; sn[t] = tn;
    __syncthreads();
    for (int o = 1; o < NT4; o <<= 1) {
        float ap = (t >= o) ? sp[t - o] : 0.f;
        float an = (t >= o) ? sn[t - o] : 0.f;
        __syncthreads();
        sp[t] += ap; sn[t] += an;
        __syncthreads();
    }
    float P = sp[t] - tp;   // exclusive cumulative positives before this thread's bins
    float N = sn[t] - tn;

    double contrib = 0.0;
    #pragma unroll
    for (int i = 0; i < PER4; i++) {
        int j = NB - 1 - (t * PER4 + i);
        float p = pc[j], n = nc[j];
        double ec = ((double)j + 0.5) * (1.0/2048.0);   // bin-center error value
        double U0 = (double)G + (double)N;
        double U1 = U0 + (double)n;
        // average of pos-first and neg-first within-bin orderings:
        if (p > 0.f) contrib += (double)p * ec * 0.5 * (1.0/U0 + 1.0/U1);
        if (n > 0.f) contrib += (double)n * ec *
                                ((double)G - (double)P - 0.5*(double)p) / (U0 * U1);
        P += p; N += n;
    }
    sctr[t] = contrib;
    __syncthreads();
    for (int o = NT4/2; o > 0; o >>= 1) {
        if (t < o) sctr[t] += sctr[t + o];
        __syncthreads();
    }
    if (t == 0) atomicAdd(&g_instl[b], sctr[0]);
}

// ---------------- pass 5: final reduction ----------------
__global__ void k5(float* __restrict__ out) {
    double li = 0.0, lv = 0.0, ls = 0.0;
    for (int b = 0; b < BN; b++) {
        li += g_instl[b] / (double)g_denom[b];
        lv += (double)g_varsum[b] / (double)g_denom[b];
        ls += (g_seedl[b] + g_bg[b]) / (double)DHW;
    }
    li /= (double)BN;
    lv = lv * 10.0 / (double)BN;   // W_VAR = 10
    ls /= (double)BN;
    out[0] = (float)li;
    out[1] = (float)lv;
    out[2] = (float)ls;
    out[3] = (float)(li + lv + ls);
}

// ---------------- launch ----------------
extern "C" void kernel_launch(void* const* d_in, const int* in_sizes, int n_in,
                              void* d_out, int out_size) {
    const float* pred = (const float*)d_in[0];
    const int*   inst = (const int*)d_in[1];
    const int*   lab  = (const int*)d_in[2];
    // d_in[3] = center_images (unused), d_in[4] = xyzm (computed analytically)

    cudaFuncSetAttribute(k3, cudaFuncAttributeMaxDynamicSharedMemorySize, 4*NB*4);

    kzero<<<256, 256>>>();
    k1<<<dim3(288, BN), 256>>>(pred, inst, lab);
    k2<<<1, 64>>>();
    k3<<<dim3(NPAIR, SLICES, BN), 512, 4*NB*4>>>();
    k4<<<NBI, NT4>>>();
    k5<<<1, 1>>>((float*)d_out);
}